// round 5
// baseline (speedup 1.0000x reference)
#include <cuda_runtime.h>
#include <math.h>
#include <stddef.h>

#define Bn  4
#define Cn  256
#define Hn  128
#define Wn  128
#define HWn (Hn*Wn)
#define WFn 65
#define Fn  (Hn*WFn)
#define NBn 6
#define GHn 128
#define ZS  131   // float2 row stride for complex FFT workspace

// ---------------- scratch -----------------------------------------------------
__device__ float  g_xt  [Bn*Cn*HWn];
__device__ float  g_spec[Bn*Cn*HWn];
__device__ float2 g_Xf  [Bn*Cn*Fn];
__device__ float2 g_Xm  [Bn*Cn*Fn];
__device__ float  g_alpha[Bn*Cn*NBn];
__device__ float  g_lwT [Cn*Cn];
__device__ int    g_bandid[Fn];
__device__ float  g_binv[NBn];
__device__ int    g_kxi, g_kyi;

__device__ __forceinline__ int brev7(int i) { return (int)(__brev((unsigned)i) >> 25); }

// ---------------- K0: setup ---------------------------------------------------
__global__ void k0_setup(const float* __restrict__ kx, const float* __restrict__ ky,
                         const float* __restrict__ lin_w) {
    __shared__ float cnt[NBn];
    int tid = threadIdx.x;
    if (tid < NBn) cnt[tid] = 0.f;
    __syncthreads();
    for (int f = tid; f < Fn; f += blockDim.x) {
        int hy = f / WFn, wx = f % WFn;
        float yy = __fdiv_rn((float)hy, 127.0f);
        float xx = __fdiv_rn((float)wx, 64.0f);
        float r  = __fsqrt_rn(__fadd_rn(__fmul_rn(yy,yy), __fmul_rn(xx,xx)));
        float rmax = __fadd_rn(__fsqrt_rn(2.0f), 1e-8f);
        float rn = __fdiv_rn(r, rmax);
        int bid = (int)floorf(__fmul_rn(rn, 6.0f));
        if (bid > NBn-1) bid = NBn-1;
        g_bandid[f] = bid;
        atomicAdd(&cnt[bid], 1.0f);
    }
    __syncthreads();
    if (tid < NBn) g_binv[tid] = 1.0f / (fmaxf(cnt[tid], 1.0f) + 1e-6f);
    if (tid == 0) {
        float sx = 1.0f / (1.0f + expf(-kx[0]));
        float sy = 1.0f / (1.0f + expf(-ky[0]));
        g_kxi = (int)floorf(sx * (float)Hn);
        g_kyi = (int)floorf(sy * (float)WFn);
    }
    for (int i = tid; i < Cn*Cn; i += blockDim.x) {
        int c = i / Cn, d = i % Cn;
        g_lwT[d*Cn + c] = lin_w[c*Cn + d];
    }
}

// ---------------- K_tr: (b,p,c) -> (b,c,p) ------------------------------------
__global__ void k_tr(const float* __restrict__ x) {
    __shared__ float tile[32][33];
    int b  = blockIdx.z;
    int c0 = blockIdx.x * 32, p0 = blockIdx.y * 32;
    int tx = threadIdx.x, ty = threadIdx.y;
    #pragma unroll
    for (int k = 0; k < 32; k += 8)
        tile[ty+k][tx] = x[((size_t)b*HWn + p0+ty+k)*Cn + c0+tx];
    __syncthreads();
    #pragma unroll
    for (int k = 0; k < 32; k += 8)
        g_xt[((size_t)b*Cn + c0+ty+k)*HWn + p0+tx] = tile[tx][ty+k];
}

// ---------------- K1: forward rfft2 (direct full-complex) ---------------------
__global__ void k1_fft() {
    extern __shared__ float2 Z[];          // [128][ZS]
    __shared__ float2 tw[64];
    int tid = threadIdx.x, nt = blockDim.x;
    int bc = blockIdx.x;

    if (tid < 64) {
        float ang = -2.0f*3.14159265358979323846f*(float)tid/128.0f;
        float s, c; sincosf(ang, &s, &c);
        tw[tid] = make_float2(c, s);
    }
    // load rows with bit-reversed column placement (input permutation)
    for (int i = tid; i < HWn; i += nt) {
        int h = i >> 7, w = i & 127;
        Z[h*ZS + brev7(w)] = make_float2(g_xt[(size_t)bc*HWn + i], 0.f);
    }
    __syncthreads();

    // full complex row FFTs (128 rows)
    for (int s = 1; s <= 7; s++) {
        int half = 1 << (s-1), step = 128 >> s;
        for (int g = tid; g < 128*64; g += nt) {
            int row = g >> 6, t2 = g & 63;
            int j = t2 & (half-1);
            int k = (t2 >> (s-1)) << s;
            float2 w = tw[j*step];
            int i0 = row*ZS + k + j, i1 = i0 + half;
            float2 u = Z[i0], x = Z[i1];
            float vr = x.x*w.x - x.y*w.y;
            float vi = x.x*w.y + x.y*w.x;
            Z[i0] = make_float2(u.x+vr, u.y+vi);
            Z[i1] = make_float2(u.x-vr, u.y-vi);
        }
        __syncthreads();
    }

    // column bit-reverse (only cols 0..64 needed)
    for (int g = tid; g < WFn*128; g += nt) {
        int i = g / WFn, col = g % WFn;
        int j = brev7(i);
        if (j > i) {
            float2 t = Z[i*ZS+col]; Z[i*ZS+col] = Z[j*ZS+col]; Z[j*ZS+col] = t;
        }
    }
    __syncthreads();
    // column FFTs (65 columns)
    for (int s = 1; s <= 7; s++) {
        int half = 1 << (s-1), step = 128 >> s;
        for (int g = tid; g < WFn*64; g += nt) {
            int col = g % WFn, t2 = g / WFn;
            int j = t2 & (half-1);
            int k = (t2 >> (s-1)) << s;
            float2 w = tw[j*step];
            int i0 = (k+j)*ZS + col, i1 = i0 + half*ZS;
            float2 u = Z[i0], x = Z[i1];
            float vr = x.x*w.x - x.y*w.y;
            float vi = x.x*w.y + x.y*w.x;
            Z[i0] = make_float2(u.x+vr, u.y+vi);
            Z[i1] = make_float2(u.x-vr, u.y-vi);
        }
        __syncthreads();
    }

    const float sc = 1.0f/128.0f;  // ortho
    for (int i = tid; i < Fn; i += nt) {
        int h = i / WFn, k = i % WFn;
        float2 v = Z[h*ZS + k];
        g_Xf[(size_t)bc*Fn + i] = make_float2(v.x*sc, v.y*sc);
    }
}

// ---------------- K2a: band means of |Xf| + MLP -> alpha ----------------------
__global__ void k2a_gate(const float* __restrict__ w1, const float* __restrict__ b1,
                         const float* __restrict__ w2, const float* __restrict__ b2) {
    __shared__ float red[NBn*256];
    __shared__ float m6[NBn];
    __shared__ float hbuf[GHn];
    int tid = threadIdx.x;
    int bc = blockIdx.x;
    float s[NBn];
    #pragma unroll
    for (int n = 0; n < NBn; n++) s[n] = 0.f;
    for (int f = tid; f < Fn; f += 256) {
        float2 z = g_Xf[(size_t)bc*Fn + f];
        float mag = sqrtf(z.x*z.x + z.y*z.y);
        int bid = g_bandid[f];
        #pragma unroll
        for (int n = 0; n < NBn; n++) s[n] += (bid == n) ? mag : 0.f;
    }
    #pragma unroll
    for (int n = 0; n < NBn; n++) red[n*256 + tid] = s[n];
    __syncthreads();
    for (int off = 128; off > 0; off >>= 1) {
        if (tid < off) {
            #pragma unroll
            for (int n = 0; n < NBn; n++) red[n*256+tid] += red[n*256+tid+off];
        }
        __syncthreads();
    }
    if (tid < NBn) m6[tid] = red[tid*256] * g_binv[tid];
    __syncthreads();
    if (tid < GHn) {
        float acc = b1[tid];
        #pragma unroll
        for (int n = 0; n < NBn; n++) acc += m6[n] * w1[tid*NBn + n];
        hbuf[tid] = fmaxf(acc, 0.f);
    }
    __syncthreads();
    if (tid < NBn) {
        float acc = b2[tid];
        for (int j = 0; j < GHn; j++) acc += hbuf[j] * w2[tid*GHn + j];
        g_alpha[bc*NBn + tid] = 1.0f / (1.0f + expf(-acc));
    }
}

// ---------------- K2b: complex channel-mix GEMM over masked freqs -------------
__global__ void k2b_mix(const float* __restrict__ wr, const float* __restrict__ wi) {
    __shared__ float2 Wt[32*16];
    __shared__ float2 Xt[16*32];
    __shared__ int    ibase[32];
    __shared__ int    okf[32];
    int kxi = g_kxi, kyi = g_kyi;
    int maskcnt = kxi * kyi;
    int Ntot = Bn * maskcnt;
    int n0 = blockIdx.y * 32;
    if (n0 >= Ntot) return;
    int c0 = blockIdx.x * 32;
    int tid = threadIdx.x;
    int tx = tid & 31, ty = tid >> 5;
    if (tid < 32) {
        int n = n0 + tid;
        if (n < Ntot) {
            int b = n / maskcnt, m = n % maskcnt;
            int hy = m / kyi, wx = m % kyi;
            ibase[tid] = b*Cn*Fn + hy*WFn + wx;
            okf[tid] = 1;
        } else { ibase[tid] = 0; okf[tid] = 0; }
    }
    __syncthreads();
    float2 acc[4];
    #pragma unroll
    for (int q = 0; q < 4; q++) acc[q] = make_float2(0.f, 0.f);
    for (int d0 = 0; d0 < Cn; d0 += 16) {
        for (int i = tid; i < 512; i += 256) {
            int cc = i >> 4, dd = i & 15;
            int gi = (c0+cc)*Cn + d0+dd;
            Wt[i] = make_float2(wr[gi], wi[gi]);
        }
        for (int i = tid; i < 512; i += 256) {
            int dd = i >> 5, j = i & 31;
            Xt[i] = okf[j] ? g_Xf[(size_t)ibase[j] + (size_t)(d0+dd)*Fn]
                           : make_float2(0.f, 0.f);
        }
        __syncthreads();
        #pragma unroll
        for (int dd = 0; dd < 16; dd++) {
            float2 xv = Xt[dd*32 + tx];
            #pragma unroll
            for (int q = 0; q < 4; q++) {
                float2 wv = Wt[(ty + 8*q)*16 + dd];
                acc[q].x += wv.x*xv.x - wv.y*xv.y;
                acc[q].y += wv.x*xv.y + wv.y*xv.x;
            }
        }
        __syncthreads();
    }
    if (okf[tx]) {
        int n = n0 + tx;
        int b = n / maskcnt;
        int f = ibase[tx] - b*Cn*Fn;
        #pragma unroll
        for (int q = 0; q < 4; q++)
            g_Xm[((size_t)(b*Cn + c0 + ty + 8*q))*Fn + f] = acc[q];
    }
}

// ---------------- K3: gated spectrum -> irfft2 (+ depthwise conv) -------------
__global__ void k3_ifft(const float* __restrict__ conv_w) {
    extern __shared__ float2 Z[];          // [128][ZS]
    __shared__ float2 tw[64];
    __shared__ float  a6[NBn];
    __shared__ float  cw[9];
    int tid = threadIdx.x, nt = blockDim.x;
    int bc = blockIdx.x;
    int c  = bc & (Cn-1);

    if (tid < 64) {
        float ang = -2.0f*3.14159265358979323846f*(float)tid/128.0f;
        float s_, c_; sincosf(ang, &s_, &c_);
        tw[tid] = make_float2(c_, s_);     // forward twiddles; conj at use
    }
    if (tid < NBn) a6[tid] = g_alpha[bc*NBn + tid];
    if (tid < 9)   cw[tid] = conv_w[c*9 + tid];
    int kxi = g_kxi, kyi = g_kyi;
    __syncthreads();

    // fused gated spectrum into cols 0..64
    for (int i = tid; i < Fn; i += nt) {
        int h = i / WFn, k = i % WFn;
        float al = a6[g_bandid[i]];
        float2 z;
        if (h < kxi && k < kyi) {
            z = g_Xm[(size_t)bc*Fn + i];
            z.x *= al; z.y *= al;
        } else {
            z = g_Xf[(size_t)bc*Fn + i];
            float om = 1.0f - al;
            z.x *= om; z.y *= om;
        }
        Z[h*ZS + k] = z;
    }
    __syncthreads();

    // inverse column FFTs (65 cols): bit-reverse then conj-twiddle butterflies
    for (int g = tid; g < WFn*128; g += nt) {
        int i = g / WFn, col = g % WFn;
        int j = brev7(i);
        if (j > i) {
            float2 t = Z[i*ZS+col]; Z[i*ZS+col] = Z[j*ZS+col]; Z[j*ZS+col] = t;
        }
    }
    __syncthreads();
    for (int s = 1; s <= 7; s++) {
        int half = 1 << (s-1), step = 128 >> s;
        for (int g = tid; g < WFn*64; g += nt) {
            int col = g % WFn, t2 = g / WFn;
            int j = t2 & (half-1);
            int k = (t2 >> (s-1)) << s;
            float2 w = tw[j*step];
            int i0 = (k+j)*ZS + col, i1 = i0 + half*ZS;
            float2 u = Z[i0], x = Z[i1];
            float vr = x.x*w.x + x.y*w.y;      // conj(w)
            float vi = x.y*w.x - x.x*w.y;
            Z[i0] = make_float2(u.x+vr, u.y+vi);
            Z[i1] = make_float2(u.x-vr, u.y-vi);
        }
        __syncthreads();
    }

    // hermitian mirror each row: cols 65..127 = conj(cols 63..1).
    // Taking Re after the full inverse then exactly reproduces C2R semantics
    // (including dropping Im of bins 0 and 64) — no special-case code.
    for (int g = tid; g < 128*63; g += nt) {
        int h = g / 63, k = 65 + (g % 63);
        float2 v = Z[h*ZS + (128 - k)];
        Z[h*ZS + k] = make_float2(v.x, -v.y);
    }
    __syncthreads();

    // inverse row FFTs (128 rows, full complex)
    for (int g = tid; g < 128*128; g += nt) {
        int h = g >> 7, i = g & 127;
        int j = brev7(i);
        if (j > i) {
            float2 t = Z[h*ZS+i]; Z[h*ZS+i] = Z[h*ZS+j]; Z[h*ZS+j] = t;
        }
    }
    __syncthreads();
    for (int s = 1; s <= 7; s++) {
        int half = 1 << (s-1), step = 128 >> s;
        for (int g = tid; g < 128*64; g += nt) {
            int row = g >> 6, t2 = g & 63;
            int j = t2 & (half-1);
            int k = (t2 >> (s-1)) << s;
            float2 w = tw[j*step];
            int i0 = row*ZS + k + j, i1 = i0 + half;
            float2 u = Z[i0], x = Z[i1];
            float vr = x.x*w.x + x.y*w.y;      // conj(w)
            float vi = x.y*w.x - x.x*w.y;
            Z[i0] = make_float2(u.x+vr, u.y+vi);
            Z[i1] = make_float2(u.x-vr, u.y-vi);
        }
        __syncthreads();
    }

    // extract Re (ortho 1/128), add depthwise 3x3 conv from g_xt, store
    const float sc = 1.0f/128.0f;
    for (int i = tid; i < HWn; i += nt) {
        int h = i >> 7, w = i & 127;
        float v = Z[h*ZS + w].x * sc;
        float cacc = 0.f;
        #pragma unroll
        for (int dy = -1; dy <= 1; dy++) {
            #pragma unroll
            for (int dx = -1; dx <= 1; dx++) {
                int hh = h+dy, ww = w+dx;
                if (hh >= 0 && hh < Hn && ww >= 0 && ww < Wn)
                    cacc += cw[(dy+1)*3 + (dx+1)] * g_xt[(size_t)bc*HWn + hh*Wn + ww];
            }
        }
        g_spec[(size_t)bc*HWn + i] = v + cacc;
    }
}

// ---------------- K4: pointwise GEMM + spec add + conditional LN --------------
__global__ void k4_final(const float* __restrict__ x,   const float* __restrict__ lin_b,
                         const float* __restrict__ tme,
                         const float* __restrict__ nww, const float* __restrict__ nwb,
                         const float* __restrict__ nbw, const float* __restrict__ nbb,
                         float* __restrict__ out) {
    extern __shared__ float sm[];
    float* xs  = sm;               // [64][256]
    float* ss  = sm + 64*Cn;       // [256][65]
    float* wsm = ss + Cn*65;       // [32][256]
    int tid = threadIdx.x;
    int b  = blockIdx.x >> 8;
    int p0 = (blockIdx.x & 255) << 6;

    for (int i = tid; i < 64*Cn; i += 256)
        xs[i] = x[((size_t)b*HWn + p0)*Cn + i];
    for (int i = tid; i < Cn*64; i += 256) {
        int c = i >> 6, pi = i & 63;
        ss[c*65 + pi] = g_spec[((size_t)(b*Cn + c))*HWn + p0 + pi];
    }
    __syncthreads();

    int tc = tid & 31, tp = tid >> 5;
    float acc8[8][8];
    #pragma unroll
    for (int q = 0; q < 8; q++) {
        int cq = tc + 32*q;
        float lb = lin_b[cq];
        #pragma unroll
        for (int r = 0; r < 8; r++)
            acc8[q][r] = lb + ss[cq*65 + tp*8 + r];
    }

    for (int d0 = 0; d0 < Cn; d0 += 32) {
        __syncthreads();
        for (int i = tid; i < 32*Cn; i += 256)
            wsm[i] = g_lwT[(size_t)d0*Cn + i];
        __syncthreads();
        #pragma unroll 4
        for (int dd = 0; dd < 32; dd++) {
            int d = d0 + dd;
            float xv[8];
            #pragma unroll
            for (int r = 0; r < 8; r++)
                xv[r] = xs[(tp*8 + r)*Cn + d];
            #pragma unroll
            for (int q = 0; q < 8; q++) {
                float wv = wsm[dd*Cn + tc + 32*q];
                #pragma unroll
                for (int r = 0; r < 8; r++)
                    acc8[q][r] += xv[r] * wv;
            }
        }
    }

    float psum[8], psq[8];
    #pragma unroll
    for (int r = 0; r < 8; r++) { psum[r] = 0.f; psq[r] = 0.f; }
    #pragma unroll
    for (int q = 0; q < 8; q++)
        #pragma unroll
        for (int r = 0; r < 8; r++) {
            psum[r] += acc8[q][r];
            psq[r]  += acc8[q][r]*acc8[q][r];
        }
    #pragma unroll
    for (int off = 16; off > 0; off >>= 1)
        #pragma unroll
        for (int r = 0; r < 8; r++) {
            psum[r] += __shfl_xor_sync(0xffffffffu, psum[r], off);
            psq[r]  += __shfl_xor_sync(0xffffffffu, psq[r],  off);
        }
    float mean[8], rstd[8];
    #pragma unroll
    for (int r = 0; r < 8; r++) {
        mean[r] = psum[r] * (1.0f/256.0f);
        float var = psq[r] * (1.0f/256.0f) - mean[r]*mean[r];
        rstd[r] = rsqrtf(var + 1e-5f);
    }
    float t = tme[b];
    #pragma unroll
    for (int q = 0; q < 8; q++) {
        int cq = tc + 32*q;
        float wc = t * nww[cq] + nwb[cq];
        float bc_ = t * nbw[cq] + nbb[cq];
        #pragma unroll
        for (int r = 0; r < 8; r++) {
            int pi = tp*8 + r;
            out[((size_t)(b*HWn + p0 + pi))*Cn + cq] =
                wc * (acc8[q][r] - mean[r]) * rstd[r] + bc_;
        }
    }
}

// ------------------------------- launch ---------------------------------------
extern "C" void kernel_launch(void* const* d_in, const int* in_sizes, int n_in,
                              void* d_out, int out_size) {
    const float* x      = (const float*)d_in[0];
    const float* tme    = (const float*)d_in[1];
    const float* w_real = (const float*)d_in[2];
    const float* w_imag = (const float*)d_in[3];
    const float* conv_w = (const float*)d_in[4];
    const float* lin_w  = (const float*)d_in[5];
    const float* lin_b  = (const float*)d_in[6];
    const float* mlp_w1 = (const float*)d_in[7];
    const float* mlp_b1 = (const float*)d_in[8];
    const float* mlp_w2 = (const float*)d_in[9];
    const float* mlp_b2 = (const float*)d_in[10];
    const float* nww    = (const float*)d_in[11];
    const float* nwb    = (const float*)d_in[12];
    const float* nbw    = (const float*)d_in[13];
    const float* nbb    = (const float*)d_in[14];
    const float* kx     = (const float*)d_in[15];
    const float* ky     = (const float*)d_in[16];
    float* out = (float*)d_out;

    const int smem_fft = Hn*ZS*8;                                   // 134,144 B
    const int smem_k4  = (64*Cn + Cn*65 + 32*Cn) * 4;               // 164,864 B
    cudaFuncSetAttribute(k1_fft,  cudaFuncAttributeMaxDynamicSharedMemorySize, smem_fft);
    cudaFuncSetAttribute(k3_ifft, cudaFuncAttributeMaxDynamicSharedMemorySize, smem_fft);
    cudaFuncSetAttribute(k4_final, cudaFuncAttributeMaxDynamicSharedMemorySize, smem_k4);

    k0_setup<<<1, 256>>>(kx, ky, lin_w);

    dim3 trg(Cn/32, HWn/32, Bn);
    k_tr<<<trg, dim3(32,8)>>>(x);

    k1_fft<<<Bn*Cn, 256, smem_fft>>>();

    k2a_gate<<<Bn*Cn, 256>>>(mlp_w1, mlp_b1, mlp_w2, mlp_b2);

    dim3 mixg(Cn/32, (Bn*Fn + 31)/32);
    k2b_mix<<<mixg, 256>>>(w_real, w_imag);

    k3_ifft<<<Bn*Cn, 256, smem_fft>>>(conv_w);

    k4_final<<<Bn*(HWn/64), 256, smem_k4>>>(x, lin_b, tme, nww, nwb, nbw, nbb, out);
}

// round 6
// speedup vs baseline: 1.2738x; 1.2738x over previous
#include <cuda_runtime.h>
#include <math.h>
#include <stddef.h>

#define Bn  4
#define Cn  256
#define Hn  128
#define Wn  128
#define HWn (Hn*Wn)
#define WFn 65
#define Fn  (Hn*WFn)
#define NBn 6
#define GHn 128
#define ZS  131   // float2 row stride for complex FFT workspace
#define NT  512   // threads for FFT kernels (compile-time for full unroll)

// ---------------- scratch -----------------------------------------------------
__device__ float  g_xt  [Bn*Cn*HWn];
__device__ float  g_spec[Bn*Cn*HWn];
__device__ float2 g_Xf  [Bn*Cn*Fn];
__device__ float2 g_Xm  [Bn*Cn*Fn];
__device__ float  g_alpha[Bn*Cn*NBn];
__device__ float  g_lwT [Cn*Cn];
__device__ int    g_bandid[Fn];
__device__ float  g_binv[NBn];
__device__ int    g_kxi, g_kyi;

__device__ __forceinline__ int brev7(int i) { return (int)(__brev((unsigned)i) >> 25); }

// ---------------- K0: setup ---------------------------------------------------
__global__ void k0_setup(const float* __restrict__ kx, const float* __restrict__ ky,
                         const float* __restrict__ lin_w) {
    __shared__ float cnt[NBn];
    int tid = threadIdx.x;
    if (tid < NBn) cnt[tid] = 0.f;
    __syncthreads();
    for (int f = tid; f < Fn; f += blockDim.x) {
        int hy = f / WFn, wx = f % WFn;
        float yy = __fdiv_rn((float)hy, 127.0f);
        float xx = __fdiv_rn((float)wx, 64.0f);
        float r  = __fsqrt_rn(__fadd_rn(__fmul_rn(yy,yy), __fmul_rn(xx,xx)));
        float rmax = __fadd_rn(__fsqrt_rn(2.0f), 1e-8f);
        float rn = __fdiv_rn(r, rmax);
        int bid = (int)floorf(__fmul_rn(rn, 6.0f));
        if (bid > NBn-1) bid = NBn-1;
        g_bandid[f] = bid;
        atomicAdd(&cnt[bid], 1.0f);
    }
    __syncthreads();
    if (tid < NBn) g_binv[tid] = 1.0f / (fmaxf(cnt[tid], 1.0f) + 1e-6f);
    if (tid == 0) {
        float sx = 1.0f / (1.0f + expf(-kx[0]));
        float sy = 1.0f / (1.0f + expf(-ky[0]));
        g_kxi = (int)floorf(sx * (float)Hn);
        g_kyi = (int)floorf(sy * (float)WFn);
    }
    for (int i = tid; i < Cn*Cn; i += blockDim.x) {
        int c = i / Cn, d = i % Cn;
        g_lwT[d*Cn + c] = lin_w[c*Cn + d];
    }
}

// ---------------- K_tr: (b,p,c) -> (b,c,p) ------------------------------------
__global__ void k_tr(const float* __restrict__ x) {
    __shared__ float tile[32][33];
    int b  = blockIdx.z;
    int c0 = blockIdx.x * 32, p0 = blockIdx.y * 32;
    int tx = threadIdx.x, ty = threadIdx.y;
    #pragma unroll
    for (int k = 0; k < 32; k += 8)
        tile[ty+k][tx] = x[((size_t)b*HWn + p0+ty+k)*Cn + c0+tx];
    __syncthreads();
    #pragma unroll
    for (int k = 0; k < 32; k += 8)
        g_xt[((size_t)b*Cn + c0+ty+k)*HWn + p0+tx] = tile[tx][ty+k];
}

// ---------------- K1: forward rfft2 (direct full-complex) + fused band gate ---
__global__ void __launch_bounds__(NT)
k1_fft(const float* __restrict__ w1, const float* __restrict__ b1,
       const float* __restrict__ w2, const float* __restrict__ b2) {
    extern __shared__ float2 Z[];          // [128][ZS]
    __shared__ float2 tw[64];
    __shared__ float  bsum[NBn];
    __shared__ float  m6[NBn];
    __shared__ float  hbuf[GHn];
    int tid = threadIdx.x;
    int bc = blockIdx.x;

    if (tid < 64) {
        float ang = -2.0f*3.14159265358979323846f*(float)tid/128.0f;
        float s, c; sincosf(ang, &s, &c);
        tw[tid] = make_float2(c, s);
    }
    if (tid < NBn) bsum[tid] = 0.f;
    // load rows with bit-reversed column placement (input permutation)
    #pragma unroll
    for (int it = 0; it < HWn/NT; it++) {
        int i = tid + it*NT;
        int h = i >> 7, w = i & 127;
        Z[h*ZS + brev7(w)] = make_float2(g_xt[(size_t)bc*HWn + i], 0.f);
    }
    __syncthreads();

    // full complex row FFTs (128 rows): 128*64 = 8192 = 16*NT exact
    for (int s = 1; s <= 7; s++) {
        int half = 1 << (s-1), step = 128 >> s;
        #pragma unroll
        for (int it = 0; it < (128*64)/NT; it++) {
            int g = tid + it*NT;
            int row = g >> 6, t2 = g & 63;
            int j = t2 & (half-1);
            int k = (t2 >> (s-1)) << s;
            float2 w = tw[j*step];
            int i0 = row*ZS + k + j, i1 = i0 + half;
            float2 u = Z[i0], x = Z[i1];
            float vr = x.x*w.x - x.y*w.y;
            float vi = x.x*w.y + x.y*w.x;
            Z[i0] = make_float2(u.x+vr, u.y+vi);
            Z[i1] = make_float2(u.x-vr, u.y-vi);
        }
        __syncthreads();
    }

    // column bit-reverse (only cols 0..64 needed): 65*128 = 8320
    #pragma unroll
    for (int it = 0; it < (WFn*128 + NT-1)/NT; it++) {
        int g = tid + it*NT;
        if (g < WFn*128) {
            int i = g / WFn, col = g % WFn;
            int j = brev7(i);
            if (j > i) {
                float2 t = Z[i*ZS+col]; Z[i*ZS+col] = Z[j*ZS+col]; Z[j*ZS+col] = t;
            }
        }
    }
    __syncthreads();
    // column FFTs (65 columns): 65*64 = 4160
    for (int s = 1; s <= 7; s++) {
        int half = 1 << (s-1), step = 128 >> s;
        #pragma unroll
        for (int it = 0; it < (WFn*64 + NT-1)/NT; it++) {
            int g = tid + it*NT;
            if (g < WFn*64) {
                int col = g % WFn, t2 = g / WFn;
                int j = t2 & (half-1);
                int k = (t2 >> (s-1)) << s;
                float2 w = tw[j*step];
                int i0 = (k+j)*ZS + col, i1 = i0 + half*ZS;
                float2 u = Z[i0], x = Z[i1];
                float vr = x.x*w.x - x.y*w.y;
                float vi = x.x*w.y + x.y*w.x;
                Z[i0] = make_float2(u.x+vr, u.y+vi);
                Z[i1] = make_float2(u.x-vr, u.y-vi);
            }
        }
        __syncthreads();
    }

    // store spectrum (ortho scale) + accumulate per-band |Xf| sums
    const float sc = 1.0f/128.0f;
    float s6[NBn];
    #pragma unroll
    for (int n = 0; n < NBn; n++) s6[n] = 0.f;
    #pragma unroll
    for (int it = 0; it < (Fn + NT-1)/NT; it++) {
        int i = tid + it*NT;
        if (i < Fn) {
            int h = i / WFn, k = i - h*WFn;
            float2 v = Z[h*ZS + k];
            v.x *= sc; v.y *= sc;
            g_Xf[(size_t)bc*Fn + i] = v;
            float mag = sqrtf(v.x*v.x + v.y*v.y);
            int bid = g_bandid[i];
            #pragma unroll
            for (int n = 0; n < NBn; n++) s6[n] += (bid == n) ? mag : 0.f;
        }
    }
    #pragma unroll
    for (int off = 16; off > 0; off >>= 1)
        #pragma unroll
        for (int n = 0; n < NBn; n++)
            s6[n] += __shfl_xor_sync(0xffffffffu, s6[n], off);
    if ((tid & 31) == 0)
        #pragma unroll
        for (int n = 0; n < NBn; n++) atomicAdd(&bsum[n], s6[n]);
    __syncthreads();

    // tiny gate MLP (per (b,c)): means -> relu(W1) -> sigmoid(W2)
    if (tid < NBn) m6[tid] = bsum[tid] * g_binv[tid];
    __syncthreads();
    if (tid < GHn) {
        float acc = b1[tid];
        #pragma unroll
        for (int n = 0; n < NBn; n++) acc += m6[n] * w1[tid*NBn + n];
        hbuf[tid] = fmaxf(acc, 0.f);
    }
    __syncthreads();
    if (tid < NBn) {
        float acc = b2[tid];
        for (int j = 0; j < GHn; j++) acc += hbuf[j] * w2[tid*GHn + j];
        g_alpha[bc*NBn + tid] = 1.0f / (1.0f + expf(-acc));
    }
}

// ---------------- K2b: complex channel-mix GEMM over masked freqs -------------
__global__ void k2b_mix(const float* __restrict__ wr, const float* __restrict__ wi) {
    __shared__ float2 Wt[32*16];
    __shared__ float2 Xt[16*32];
    __shared__ int    ibase[32];
    __shared__ int    okf[32];
    int kxi = g_kxi, kyi = g_kyi;
    int maskcnt = kxi * kyi;
    int Ntot = Bn * maskcnt;
    int n0 = blockIdx.y * 32;
    if (n0 >= Ntot) return;
    int c0 = blockIdx.x * 32;
    int tid = threadIdx.x;
    int tx = tid & 31, ty = tid >> 5;
    if (tid < 32) {
        int n = n0 + tid;
        if (n < Ntot) {
            int b = n / maskcnt, m = n % maskcnt;
            int hy = m / kyi, wx = m % kyi;
            ibase[tid] = b*Cn*Fn + hy*WFn + wx;
            okf[tid] = 1;
        } else { ibase[tid] = 0; okf[tid] = 0; }
    }
    __syncthreads();
    float2 acc[4];
    #pragma unroll
    for (int q = 0; q < 4; q++) acc[q] = make_float2(0.f, 0.f);
    for (int d0 = 0; d0 < Cn; d0 += 16) {
        #pragma unroll
        for (int i0 = 0; i0 < 2; i0++) {
            int i = tid + i0*256;
            int cc = i >> 4, dd = i & 15;
            int gi = (c0+cc)*Cn + d0+dd;
            Wt[i] = make_float2(wr[gi], wi[gi]);
        }
        #pragma unroll
        for (int i0 = 0; i0 < 2; i0++) {
            int i = tid + i0*256;
            int dd = i >> 5, j = i & 31;
            Xt[i] = okf[j] ? g_Xf[(size_t)ibase[j] + (size_t)(d0+dd)*Fn]
                           : make_float2(0.f, 0.f);
        }
        __syncthreads();
        #pragma unroll
        for (int dd = 0; dd < 16; dd++) {
            float2 xv = Xt[dd*32 + tx];
            #pragma unroll
            for (int q = 0; q < 4; q++) {
                float2 wv = Wt[(ty + 8*q)*16 + dd];
                acc[q].x += wv.x*xv.x - wv.y*xv.y;
                acc[q].y += wv.x*xv.y + wv.y*xv.x;
            }
        }
        __syncthreads();
    }
    if (okf[tx]) {
        int n = n0 + tx;
        int b = n / maskcnt;
        int f = ibase[tx] - b*Cn*Fn;
        #pragma unroll
        for (int q = 0; q < 4; q++)
            g_Xm[((size_t)(b*Cn + c0 + ty + 8*q))*Fn + f] = acc[q];
    }
}

// ---------------- K3: gated spectrum -> irfft2 (+ depthwise conv) -------------
__global__ void __launch_bounds__(NT)
k3_ifft(const float* __restrict__ conv_w) {
    extern __shared__ float2 Z[];          // [128][ZS]
    __shared__ float2 tw[64];
    __shared__ float  a6[NBn];
    __shared__ float  cw[9];
    int tid = threadIdx.x;
    int bc = blockIdx.x;
    int c  = bc & (Cn-1);

    if (tid < 64) {
        float ang = -2.0f*3.14159265358979323846f*(float)tid/128.0f;
        float s_, c_; sincosf(ang, &s_, &c_);
        tw[tid] = make_float2(c_, s_);     // forward twiddles; conj at use
    }
    if (tid < NBn) a6[tid] = g_alpha[bc*NBn + tid];
    if (tid < 9)   cw[tid] = conv_w[c*9 + tid];
    int kxi = g_kxi, kyi = g_kyi;
    __syncthreads();

    // fused gated spectrum into cols 0..64
    #pragma unroll
    for (int it = 0; it < (Fn + NT-1)/NT; it++) {
        int i = tid + it*NT;
        if (i < Fn) {
            int h = i / WFn, k = i - h*WFn;
            float al = a6[g_bandid[i]];
            float2 z;
            if (h < kxi && k < kyi) {
                z = g_Xm[(size_t)bc*Fn + i];
                z.x *= al; z.y *= al;
            } else {
                z = g_Xf[(size_t)bc*Fn + i];
                float om = 1.0f - al;
                z.x *= om; z.y *= om;
            }
            Z[h*ZS + k] = z;
        }
    }
    __syncthreads();

    // inverse column FFTs (65 cols)
    #pragma unroll
    for (int it = 0; it < (WFn*128 + NT-1)/NT; it++) {
        int g = tid + it*NT;
        if (g < WFn*128) {
            int i = g / WFn, col = g % WFn;
            int j = brev7(i);
            if (j > i) {
                float2 t = Z[i*ZS+col]; Z[i*ZS+col] = Z[j*ZS+col]; Z[j*ZS+col] = t;
            }
        }
    }
    __syncthreads();
    for (int s = 1; s <= 7; s++) {
        int half = 1 << (s-1), step = 128 >> s;
        #pragma unroll
        for (int it = 0; it < (WFn*64 + NT-1)/NT; it++) {
            int g = tid + it*NT;
            if (g < WFn*64) {
                int col = g % WFn, t2 = g / WFn;
                int j = t2 & (half-1);
                int k = (t2 >> (s-1)) << s;
                float2 w = tw[j*step];
                int i0 = (k+j)*ZS + col, i1 = i0 + half*ZS;
                float2 u = Z[i0], x = Z[i1];
                float vr = x.x*w.x + x.y*w.y;      // conj(w)
                float vi = x.y*w.x - x.x*w.y;
                Z[i0] = make_float2(u.x+vr, u.y+vi);
                Z[i1] = make_float2(u.x-vr, u.y-vi);
            }
        }
        __syncthreads();
    }

    // hermitian mirror each row: cols 65..127 = conj(cols 63..1).
    // Re of full inverse == C2R semantics (incl. dropping Im of bins 0,64).
    #pragma unroll
    for (int it = 0; it < (128*63 + NT-1)/NT; it++) {
        int g = tid + it*NT;
        if (g < 128*63) {
            int h = g / 63, k = 65 + (g % 63);
            float2 v = Z[h*ZS + (128 - k)];
            Z[h*ZS + k] = make_float2(v.x, -v.y);
        }
    }
    __syncthreads();

    // inverse row FFTs (128 rows, full complex)
    #pragma unroll
    for (int it = 0; it < (128*128)/NT; it++) {
        int g = tid + it*NT;
        int h = g >> 7, i = g & 127;
        int j = brev7(i);
        if (j > i) {
            float2 t = Z[h*ZS+i]; Z[h*ZS+i] = Z[h*ZS+j]; Z[h*ZS+j] = t;
        }
    }
    __syncthreads();
    for (int s = 1; s <= 7; s++) {
        int half = 1 << (s-1), step = 128 >> s;
        #pragma unroll
        for (int it = 0; it < (128*64)/NT; it++) {
            int g = tid + it*NT;
            int row = g >> 6, t2 = g & 63;
            int j = t2 & (half-1);
            int k = (t2 >> (s-1)) << s;
            float2 w = tw[j*step];
            int i0 = row*ZS + k + j, i1 = i0 + half;
            float2 u = Z[i0], x = Z[i1];
            float vr = x.x*w.x + x.y*w.y;      // conj(w)
            float vi = x.y*w.x - x.x*w.y;
            Z[i0] = make_float2(u.x+vr, u.y+vi);
            Z[i1] = make_float2(u.x-vr, u.y-vi);
        }
        __syncthreads();
    }

    // extract Re (ortho 1/128), add depthwise 3x3 conv from g_xt, store
    const float sc = 1.0f/128.0f;
    #pragma unroll
    for (int it = 0; it < HWn/NT; it++) {
        int i = tid + it*NT;
        int h = i >> 7, w = i & 127;
        float v = Z[h*ZS + w].x * sc;
        float cacc = 0.f;
        #pragma unroll
        for (int dy = -1; dy <= 1; dy++) {
            #pragma unroll
            for (int dx = -1; dx <= 1; dx++) {
                int hh = h+dy, ww = w+dx;
                if (hh >= 0 && hh < Hn && ww >= 0 && ww < Wn)
                    cacc += cw[(dy+1)*3 + (dx+1)] * g_xt[(size_t)bc*HWn + hh*Wn + ww];
            }
        }
        g_spec[(size_t)bc*HWn + i] = v + cacc;
    }
}

// ---------------- K4: pointwise GEMM + spec add + conditional LN --------------
__global__ void k4_final(const float* __restrict__ x,   const float* __restrict__ lin_b,
                         const float* __restrict__ tme,
                         const float* __restrict__ nww, const float* __restrict__ nwb,
                         const float* __restrict__ nbw, const float* __restrict__ nbb,
                         float* __restrict__ out) {
    extern __shared__ float sm[];
    float* xs  = sm;               // [64][256]
    float* ss  = sm + 64*Cn;       // [256][65]
    float* wsm = ss + Cn*65;       // [32][256]
    int tid = threadIdx.x;
    int b  = blockIdx.x >> 8;
    int p0 = (blockIdx.x & 255) << 6;

    for (int i = tid; i < 64*Cn; i += 256)
        xs[i] = x[((size_t)b*HWn + p0)*Cn + i];
    for (int i = tid; i < Cn*64; i += 256) {
        int c = i >> 6, pi = i & 63;
        ss[c*65 + pi] = g_spec[((size_t)(b*Cn + c))*HWn + p0 + pi];
    }
    __syncthreads();

    int tc = tid & 31, tp = tid >> 5;
    float acc8[8][8];
    #pragma unroll
    for (int q = 0; q < 8; q++) {
        int cq = tc + 32*q;
        float lb = lin_b[cq];
        #pragma unroll
        for (int r = 0; r < 8; r++)
            acc8[q][r] = lb + ss[cq*65 + tp*8 + r];
    }

    for (int d0 = 0; d0 < Cn; d0 += 32) {
        __syncthreads();
        for (int i = tid; i < 32*Cn; i += 256)
            wsm[i] = g_lwT[(size_t)d0*Cn + i];
        __syncthreads();
        #pragma unroll 4
        for (int dd = 0; dd < 32; dd++) {
            int d = d0 + dd;
            float xv[8];
            #pragma unroll
            for (int r = 0; r < 8; r++)
                xv[r] = xs[(tp*8 + r)*Cn + d];
            #pragma unroll
            for (int q = 0; q < 8; q++) {
                float wv = wsm[dd*Cn + tc + 32*q];
                #pragma unroll
                for (int r = 0; r < 8; r++)
                    acc8[q][r] += xv[r] * wv;
            }
        }
    }

    float psum[8], psq[8];
    #pragma unroll
    for (int r = 0; r < 8; r++) { psum[r] = 0.f; psq[r] = 0.f; }
    #pragma unroll
    for (int q = 0; q < 8; q++)
        #pragma unroll
        for (int r = 0; r < 8; r++) {
            psum[r] += acc8[q][r];
            psq[r]  += acc8[q][r]*acc8[q][r];
        }
    #pragma unroll
    for (int off = 16; off > 0; off >>= 1)
        #pragma unroll
        for (int r = 0; r < 8; r++) {
            psum[r] += __shfl_xor_sync(0xffffffffu, psum[r], off);
            psq[r]  += __shfl_xor_sync(0xffffffffu, psq[r],  off);
        }
    float mean[8], rstd[8];
    #pragma unroll
    for (int r = 0; r < 8; r++) {
        mean[r] = psum[r] * (1.0f/256.0f);
        float var = psq[r] * (1.0f/256.0f) - mean[r]*mean[r];
        rstd[r] = rsqrtf(var + 1e-5f);
    }
    float t = tme[b];
    #pragma unroll
    for (int q = 0; q < 8; q++) {
        int cq = tc + 32*q;
        float wc = t * nww[cq] + nwb[cq];
        float bc_ = t * nbw[cq] + nbb[cq];
        #pragma unroll
        for (int r = 0; r < 8; r++) {
            int pi = tp*8 + r;
            out[((size_t)(b*HWn + p0 + pi))*Cn + cq] =
                wc * (acc8[q][r] - mean[r]) * rstd[r] + bc_;
        }
    }
}

// ------------------------------- launch ---------------------------------------
extern "C" void kernel_launch(void* const* d_in, const int* in_sizes, int n_in,
                              void* d_out, int out_size) {
    const float* x      = (const float*)d_in[0];
    const float* tme    = (const float*)d_in[1];
    const float* w_real = (const float*)d_in[2];
    const float* w_imag = (const float*)d_in[3];
    const float* conv_w = (const float*)d_in[4];
    const float* lin_w  = (const float*)d_in[5];
    const float* lin_b  = (const float*)d_in[6];
    const float* mlp_w1 = (const float*)d_in[7];
    const float* mlp_b1 = (const float*)d_in[8];
    const float* mlp_w2 = (const float*)d_in[9];
    const float* mlp_b2 = (const float*)d_in[10];
    const float* nww    = (const float*)d_in[11];
    const float* nwb    = (const float*)d_in[12];
    const float* nbw    = (const float*)d_in[13];
    const float* nbb    = (const float*)d_in[14];
    const float* kx     = (const float*)d_in[15];
    const float* ky     = (const float*)d_in[16];
    float* out = (float*)d_out;

    const int smem_fft = Hn*ZS*8;                                   // 134,144 B
    const int smem_k4  = (64*Cn + Cn*65 + 32*Cn) * 4;               // 164,864 B
    cudaFuncSetAttribute(k1_fft,  cudaFuncAttributeMaxDynamicSharedMemorySize, smem_fft);
    cudaFuncSetAttribute(k3_ifft, cudaFuncAttributeMaxDynamicSharedMemorySize, smem_fft);
    cudaFuncSetAttribute(k4_final, cudaFuncAttributeMaxDynamicSharedMemorySize, smem_k4);

    k0_setup<<<1, 256>>>(kx, ky, lin_w);

    dim3 trg(Cn/32, HWn/32, Bn);
    k_tr<<<trg, dim3(32,8)>>>(x);

    k1_fft<<<Bn*Cn, NT, smem_fft>>>(mlp_w1, mlp_b1, mlp_w2, mlp_b2);

    dim3 mixg(Cn/32, (Bn*Fn + 31)/32);
    k2b_mix<<<mixg, 256>>>(w_real, w_imag);

    k3_ifft<<<Bn*Cn, NT, smem_fft>>>(conv_w);

    k4_final<<<Bn*(HWn/64), 256, smem_k4>>>(x, lin_b, tme, nww, nwb, nbw, nbb, out);
}

// round 8
// speedup vs baseline: 1.3528x; 1.0620x over previous
#include <cuda_runtime.h>
#include <math.h>
#include <stddef.h>

#define Bn  4
#define Cn  256
#define Hn  128
#define Wn  128
#define HWn (Hn*Wn)
#define WFn 65
#define Fn  (Hn*WFn)
#define NBn 6
#define GHn 128
#define ZS  131   // float2 row stride for complex FFT workspace
#define NT  512   // threads for FFT kernels (compile-time for full unroll)

typedef unsigned long long u64;

// ---------------- scratch -----------------------------------------------------
__device__ float  g_xt  [Bn*Cn*HWn];
__device__ float  g_spec[Bn*Cn*HWn];
__device__ float2 g_Xf  [Bn*Cn*Fn];
__device__ float2 g_Xm  [Bn*Cn*Fn];
__device__ float  g_alpha[Bn*Cn*NBn];
__device__ float  g_lwT [Cn*Cn];
__device__ int    g_bandid[Fn];
__device__ float  g_binv[NBn];
__device__ int    g_kxi, g_kyi;

__device__ __forceinline__ int brev7(int i) { return (int)(__brev((unsigned)i) >> 25); }

__device__ __forceinline__ float2 cmul(float2 a, float2 w) {
    return make_float2(a.x*w.x - a.y*w.y, a.x*w.y + a.y*w.x);
}
__device__ __forceinline__ float2 cmulc(float2 a, float2 w) {   // a * conj(w)
    return make_float2(a.x*w.x + a.y*w.y, a.y*w.x - a.x*w.y);
}

// radix-2^2: two radix-2 stages (s, s+1) applied in registers.
// inputs at base, base+half, base+2half, base+3half; w1 = tw[j*step],
// wA = tw[j*step2]; wB = tw[j*step2+32] = (wA.y, -wA.x).
__device__ __forceinline__ void bf4_fwd(float2& x0, float2& x1, float2& x2, float2& x3,
                                        float2 w1, float2 wA) {
    float2 wB = make_float2(wA.y, -wA.x);
    float2 v1 = cmul(x1, w1), v3 = cmul(x3, w1);
    float2 a0 = make_float2(x0.x+v1.x, x0.y+v1.y);
    float2 a1 = make_float2(x0.x-v1.x, x0.y-v1.y);
    float2 a2 = make_float2(x2.x+v3.x, x2.y+v3.y);
    float2 a3 = make_float2(x2.x-v3.x, x2.y-v3.y);
    float2 v2 = cmul(a2, wA), v4 = cmul(a3, wB);
    x0 = make_float2(a0.x+v2.x, a0.y+v2.y);
    x2 = make_float2(a0.x-v2.x, a0.y-v2.y);
    x1 = make_float2(a1.x+v4.x, a1.y+v4.y);
    x3 = make_float2(a1.x-v4.x, a1.y-v4.y);
}
__device__ __forceinline__ void bf4_inv(float2& x0, float2& x1, float2& x2, float2& x3,
                                        float2 w1, float2 wA) {
    float2 wB = make_float2(wA.y, -wA.x);   // cmulc conjugates -> conj(tw[j*step2+32])
    float2 v1 = cmulc(x1, w1), v3 = cmulc(x3, w1);
    float2 a0 = make_float2(x0.x+v1.x, x0.y+v1.y);
    float2 a1 = make_float2(x0.x-v1.x, x0.y-v1.y);
    float2 a2 = make_float2(x2.x+v3.x, x2.y+v3.y);
    float2 a3 = make_float2(x2.x-v3.x, x2.y-v3.y);
    float2 v2 = cmulc(a2, wA), v4 = cmulc(a3, wB);
    x0 = make_float2(a0.x+v2.x, a0.y+v2.y);
    x2 = make_float2(a0.x-v2.x, a0.y-v2.y);
    x1 = make_float2(a1.x+v4.x, a1.y+v4.y);
    x3 = make_float2(a1.x-v4.x, a1.y-v4.y);
}

// packed f32x2 helpers (FFMA2 path — only reachable via PTX)
__device__ __forceinline__ u64 pk2(float lo, float hi) {
    u64 r; asm("mov.b64 %0, {%1,%2};" : "=l"(r) : "f"(lo), "f"(hi)); return r;
}
__device__ __forceinline__ float2 upk2(u64 v) {
    float lo, hi; asm("mov.b64 {%0,%1}, %2;" : "=f"(lo), "=f"(hi) : "l"(v));
    return make_float2(lo, hi);
}
#define FMA2(d, a, b, c) asm("fma.rn.f32x2 %0, %1, %2, %3;" : "=l"(d) : "l"(a), "l"(b), "l"(c))

// ---------------- K0: setup ---------------------------------------------------
__global__ void k0_setup(const float* __restrict__ kx, const float* __restrict__ ky,
                         const float* __restrict__ lin_w) {
    __shared__ float cnt[NBn];
    int tid = threadIdx.x;
    if (tid < NBn) cnt[tid] = 0.f;
    __syncthreads();
    for (int f = tid; f < Fn; f += blockDim.x) {
        int hy = f / WFn, wx = f % WFn;
        float yy = __fdiv_rn((float)hy, 127.0f);
        float xx = __fdiv_rn((float)wx, 64.0f);
        float r  = __fsqrt_rn(__fadd_rn(__fmul_rn(yy,yy), __fmul_rn(xx,xx)));
        float rmax = __fadd_rn(__fsqrt_rn(2.0f), 1e-8f);
        float rn = __fdiv_rn(r, rmax);
        int bid = (int)floorf(__fmul_rn(rn, 6.0f));
        if (bid > NBn-1) bid = NBn-1;
        g_bandid[f] = bid;
        atomicAdd(&cnt[bid], 1.0f);
    }
    __syncthreads();
    if (tid < NBn) g_binv[tid] = 1.0f / (fmaxf(cnt[tid], 1.0f) + 1e-6f);
    if (tid == 0) {
        float sx = 1.0f / (1.0f + expf(-kx[0]));
        float sy = 1.0f / (1.0f + expf(-ky[0]));
        g_kxi = (int)floorf(sx * (float)Hn);
        g_kyi = (int)floorf(sy * (float)WFn);
    }
    for (int i = tid; i < Cn*Cn; i += blockDim.x) {
        int c = i / Cn, d = i % Cn;
        g_lwT[d*Cn + c] = lin_w[c*Cn + d];
    }
}

// ---------------- K_tr: (b,p,c) -> (b,c,p) ------------------------------------
__global__ void k_tr(const float* __restrict__ x) {
    __shared__ float tile[32][33];
    int b  = blockIdx.z;
    int c0 = blockIdx.x * 32, p0 = blockIdx.y * 32;
    int tx = threadIdx.x, ty = threadIdx.y;
    #pragma unroll
    for (int k = 0; k < 32; k += 8)
        tile[ty+k][tx] = x[((size_t)b*HWn + p0+ty+k)*Cn + c0+tx];
    __syncthreads();
    #pragma unroll
    for (int k = 0; k < 32; k += 8)
        g_xt[((size_t)b*Cn + c0+ty+k)*HWn + p0+tx] = tile[tx][ty+k];
}

// ---------------- K1: forward rfft2 + fused band gate -------------------------
__global__ void __launch_bounds__(NT)
k1_fft(const float* __restrict__ w1p, const float* __restrict__ b1,
       const float* __restrict__ w2p, const float* __restrict__ b2) {
    extern __shared__ float2 Z[];          // [128][ZS]
    __shared__ float2 tw[64];
    __shared__ float  bsum[NBn];
    __shared__ float  m6[NBn];
    __shared__ float  hbuf[GHn];
    int tid = threadIdx.x;
    int bc = blockIdx.x;

    if (tid < 64) {
        float ang = -2.0f*3.14159265358979323846f*(float)tid/128.0f;
        float s, c; sincosf(ang, &s, &c);
        tw[tid] = make_float2(c, s);
    }
    if (tid < NBn) bsum[tid] = 0.f;
    #pragma unroll
    for (int it = 0; it < HWn/NT; it++) {
        int i = tid + it*NT;
        int h = i >> 7, w = i & 127;
        Z[h*ZS + brev7(w)] = make_float2(g_xt[(size_t)bc*HWn + i], 0.f);
    }
    __syncthreads();

    // row FFTs: fused stage pairs (1,2),(3,4),(5,6); 128 rows x 32 groups = 4096
    #pragma unroll
    for (int s = 1; s <= 5; s += 2) {
        int half = 1 << (s-1), step = 128 >> s, step2 = step >> 1;
        #pragma unroll
        for (int it = 0; it < 4096/NT; it++) {
            int g = tid + it*NT;
            int row = g >> 5, t = g & 31;
            int j = t & (half-1);
            int base = row*ZS + (((t >> (s-1)) << (s+1)) + j);
            float2 x0 = Z[base], x1 = Z[base+half], x2 = Z[base+2*half], x3 = Z[base+3*half];
            bf4_fwd(x0, x1, x2, x3, tw[j*step], tw[j*step2]);
            Z[base] = x0; Z[base+half] = x1; Z[base+2*half] = x2; Z[base+3*half] = x3;
        }
        __syncthreads();
    }
    {   // row stage 7: half=64, step=1
        #pragma unroll
        for (int it = 0; it < 8192/NT; it++) {
            int g = tid + it*NT;
            int row = g >> 6, j = g & 63;
            int i0 = row*ZS + j, i1 = i0 + 64;
            float2 w = tw[j];
            float2 u = Z[i0], x = Z[i1];
            float2 v = cmul(x, w);
            Z[i0] = make_float2(u.x+v.x, u.y+v.y);
            Z[i1] = make_float2(u.x-v.x, u.y-v.y);
        }
        __syncthreads();
    }

    // column bit-reverse (cols 0..64)
    #pragma unroll
    for (int it = 0; it < (WFn*128 + NT-1)/NT; it++) {
        int g = tid + it*NT;
        if (g < WFn*128) {
            int i = g / WFn, col = g % WFn;
            int j = brev7(i);
            if (j > i) {
                float2 t = Z[i*ZS+col]; Z[i*ZS+col] = Z[j*ZS+col]; Z[j*ZS+col] = t;
            }
        }
    }
    __syncthreads();
    // column FFTs: fused pairs; 65 cols x 32 groups = 2080
    #pragma unroll
    for (int s = 1; s <= 5; s += 2) {
        int half = 1 << (s-1), step = 128 >> s, step2 = step >> 1;
        #pragma unroll
        for (int it = 0; it < (2080 + NT-1)/NT; it++) {
            int g = tid + it*NT;
            if (g < 2080) {
                int col = g % WFn, t = g / WFn;
                int j = t & (half-1);
                int base = (((t >> (s-1)) << (s+1)) + j)*ZS + col;
                int hs = half*ZS;
                float2 x0 = Z[base], x1 = Z[base+hs], x2 = Z[base+2*hs], x3 = Z[base+3*hs];
                bf4_fwd(x0, x1, x2, x3, tw[j*step], tw[j*step2]);
                Z[base] = x0; Z[base+hs] = x1; Z[base+2*hs] = x2; Z[base+3*hs] = x3;
            }
        }
        __syncthreads();
    }
    {   // column stage 7: pairs (j, j+64) per column; 65*64 = 4160
        #pragma unroll
        for (int it = 0; it < (4160 + NT-1)/NT; it++) {
            int g = tid + it*NT;
            if (g < 4160) {
                int col = g % WFn, j = g / WFn;
                int i0 = j*ZS + col, i1 = i0 + 64*ZS;
                float2 w = tw[j];
                float2 u = Z[i0], x = Z[i1];
                float2 v = cmul(x, w);
                Z[i0] = make_float2(u.x+v.x, u.y+v.y);
                Z[i1] = make_float2(u.x-v.x, u.y-v.y);
            }
        }
        __syncthreads();
    }

    // store spectrum (ortho scale) + per-band |Xf| sums
    const float sc = 1.0f/128.0f;
    float s6[NBn];
    #pragma unroll
    for (int n = 0; n < NBn; n++) s6[n] = 0.f;
    #pragma unroll
    for (int it = 0; it < (Fn + NT-1)/NT; it++) {
        int i = tid + it*NT;
        if (i < Fn) {
            int h = i / WFn, k = i - h*WFn;
            float2 v = Z[h*ZS + k];
            v.x *= sc; v.y *= sc;
            g_Xf[(size_t)bc*Fn + i] = v;
            float mag = sqrtf(v.x*v.x + v.y*v.y);
            int bid = g_bandid[i];
            #pragma unroll
            for (int n = 0; n < NBn; n++) s6[n] += (bid == n) ? mag : 0.f;
        }
    }
    #pragma unroll
    for (int off = 16; off > 0; off >>= 1)
        #pragma unroll
        for (int n = 0; n < NBn; n++)
            s6[n] += __shfl_xor_sync(0xffffffffu, s6[n], off);
    if ((tid & 31) == 0)
        #pragma unroll
        for (int n = 0; n < NBn; n++) atomicAdd(&bsum[n], s6[n]);
    __syncthreads();

    if (tid < NBn) m6[tid] = bsum[tid] * g_binv[tid];
    __syncthreads();
    if (tid < GHn) {
        float acc = b1[tid];
        #pragma unroll
        for (int n = 0; n < NBn; n++) acc += m6[n] * w1p[tid*NBn + n];
        hbuf[tid] = fmaxf(acc, 0.f);
    }
    __syncthreads();
    if (tid < NBn) {
        float acc = b2[tid];
        for (int j = 0; j < GHn; j++) acc += hbuf[j] * w2p[tid*GHn + j];
        g_alpha[bc*NBn + tid] = 1.0f / (1.0f + expf(-acc));
    }
}

// ---------------- K2b: complex channel-mix GEMM over masked freqs -------------
__global__ void k2b_mix(const float* __restrict__ wr, const float* __restrict__ wi) {
    __shared__ float2 Wt[32*16];
    __shared__ float2 Xt[16*32];
    __shared__ int    ibase[32];
    __shared__ int    okf[32];
    int kxi = g_kxi, kyi = g_kyi;
    int maskcnt = kxi * kyi;
    int Ntot = Bn * maskcnt;
    int n0 = blockIdx.y * 32;
    if (n0 >= Ntot) return;
    int c0 = blockIdx.x * 32;
    int tid = threadIdx.x;
    int tx = tid & 31, ty = tid >> 5;
    if (tid < 32) {
        int n = n0 + tid;
        if (n < Ntot) {
            int b = n / maskcnt, m = n % maskcnt;
            int hy = m / kyi, wx = m % kyi;
            ibase[tid] = b*Cn*Fn + hy*WFn + wx;
            okf[tid] = 1;
        } else { ibase[tid] = 0; okf[tid] = 0; }
    }
    __syncthreads();
    float2 acc[4];
    #pragma unroll
    for (int q = 0; q < 4; q++) acc[q] = make_float2(0.f, 0.f);
    for (int d0 = 0; d0 < Cn; d0 += 16) {
        #pragma unroll
        for (int i0 = 0; i0 < 2; i0++) {
            int i = tid + i0*256;
            int cc = i >> 4, dd = i & 15;
            int gi = (c0+cc)*Cn + d0+dd;
            Wt[i] = make_float2(wr[gi], wi[gi]);
        }
        #pragma unroll
        for (int i0 = 0; i0 < 2; i0++) {
            int i = tid + i0*256;
            int dd = i >> 5, j = i & 31;
            Xt[i] = okf[j] ? g_Xf[(size_t)ibase[j] + (size_t)(d0+dd)*Fn]
                           : make_float2(0.f, 0.f);
        }
        __syncthreads();
        #pragma unroll
        for (int dd = 0; dd < 16; dd++) {
            float2 xv = Xt[dd*32 + tx];
            #pragma unroll
            for (int q = 0; q < 4; q++) {
                float2 wv = Wt[(ty + 8*q)*16 + dd];
                acc[q].x += wv.x*xv.x - wv.y*xv.y;
                acc[q].y += wv.x*xv.y + wv.y*xv.x;
            }
        }
        __syncthreads();
    }
    if (okf[tx]) {
        int n = n0 + tx;
        int b = n / maskcnt;
        int f = ibase[tx] - b*Cn*Fn;
        #pragma unroll
        for (int q = 0; q < 4; q++)
            g_Xm[((size_t)(b*Cn + c0 + ty + 8*q))*Fn + f] = acc[q];
    }
}

// ---------------- K3: gated spectrum -> irfft2 (+ depthwise conv) -------------
__global__ void __launch_bounds__(NT)
k3_ifft(const float* __restrict__ conv_w) {
    extern __shared__ float2 Z[];          // [128][ZS]
    __shared__ float2 tw[64];
    __shared__ float  a6[NBn];
    __shared__ float  cw[9];
    int tid = threadIdx.x;
    int bc = blockIdx.x;
    int c  = bc & (Cn-1);

    if (tid < 64) {
        float ang = -2.0f*3.14159265358979323846f*(float)tid/128.0f;
        float s_, c_; sincosf(ang, &s_, &c_);
        tw[tid] = make_float2(c_, s_);     // forward twiddles; conj at use
    }
    if (tid < NBn) a6[tid] = g_alpha[bc*NBn + tid];
    if (tid < 9)   cw[tid] = conv_w[c*9 + tid];
    int kxi = g_kxi, kyi = g_kyi;
    __syncthreads();

    // fused gated spectrum into cols 0..64
    #pragma unroll
    for (int it = 0; it < (Fn + NT-1)/NT; it++) {
        int i = tid + it*NT;
        if (i < Fn) {
            int h = i / WFn, k = i - h*WFn;
            float al = a6[g_bandid[i]];
            float2 z;
            if (h < kxi && k < kyi) {
                z = g_Xm[(size_t)bc*Fn + i];
                z.x *= al; z.y *= al;
            } else {
                z = g_Xf[(size_t)bc*Fn + i];
                float om = 1.0f - al;
                z.x *= om; z.y *= om;
            }
            Z[h*ZS + k] = z;
        }
    }
    __syncthreads();

    // inverse column FFTs: bit-reverse, fused pairs, stage 7
    #pragma unroll
    for (int it = 0; it < (WFn*128 + NT-1)/NT; it++) {
        int g = tid + it*NT;
        if (g < WFn*128) {
            int i = g / WFn, col = g % WFn;
            int j = brev7(i);
            if (j > i) {
                float2 t = Z[i*ZS+col]; Z[i*ZS+col] = Z[j*ZS+col]; Z[j*ZS+col] = t;
            }
        }
    }
    __syncthreads();
    #pragma unroll
    for (int s = 1; s <= 5; s += 2) {
        int half = 1 << (s-1), step = 128 >> s, step2 = step >> 1;
        #pragma unroll
        for (int it = 0; it < (2080 + NT-1)/NT; it++) {
            int g = tid + it*NT;
            if (g < 2080) {
                int col = g % WFn, t = g / WFn;
                int j = t & (half-1);
                int base = (((t >> (s-1)) << (s+1)) + j)*ZS + col;
                int hs = half*ZS;
                float2 x0 = Z[base], x1 = Z[base+hs], x2 = Z[base+2*hs], x3 = Z[base+3*hs];
                bf4_inv(x0, x1, x2, x3, tw[j*step], tw[j*step2]);
                Z[base] = x0; Z[base+hs] = x1; Z[base+2*hs] = x2; Z[base+3*hs] = x3;
            }
        }
        __syncthreads();
    }
    {
        #pragma unroll
        for (int it = 0; it < (4160 + NT-1)/NT; it++) {
            int g = tid + it*NT;
            if (g < 4160) {
                int col = g % WFn, j = g / WFn;
                int i0 = j*ZS + col, i1 = i0 + 64*ZS;
                float2 u = Z[i0], x = Z[i1];
                float2 v = cmulc(x, tw[j]);
                Z[i0] = make_float2(u.x+v.x, u.y+v.y);
                Z[i1] = make_float2(u.x-v.x, u.y-v.y);
            }
        }
        __syncthreads();
    }

    // hermitian mirror each row: cols 65..127 = conj(cols 63..1).
    // Re of full inverse == C2R semantics (incl. dropping Im of bins 0,64).
    #pragma unroll
    for (int it = 0; it < (128*63 + NT-1)/NT; it++) {
        int g = tid + it*NT;
        if (g < 128*63) {
            int h = g / 63, k = 65 + (g % 63);
            float2 v = Z[h*ZS + (128 - k)];
            Z[h*ZS + k] = make_float2(v.x, -v.y);
        }
    }
    __syncthreads();

    // inverse row FFTs: bit-reverse, fused pairs, stage 7
    #pragma unroll
    for (int it = 0; it < (128*128)/NT; it++) {
        int g = tid + it*NT;
        int h = g >> 7, i = g & 127;
        int j = brev7(i);
        if (j > i) {
            float2 t = Z[h*ZS+i]; Z[h*ZS+i] = Z[h*ZS+j]; Z[h*ZS+j] = t;
        }
    }
    __syncthreads();
    #pragma unroll
    for (int s = 1; s <= 5; s += 2) {
        int half = 1 << (s-1), step = 128 >> s, step2 = step >> 1;
        #pragma unroll
        for (int it = 0; it < 4096/NT; it++) {
            int g = tid + it*NT;
            int row = g >> 5, t = g & 31;
            int j = t & (half-1);
            int base = row*ZS + (((t >> (s-1)) << (s+1)) + j);
            float2 x0 = Z[base], x1 = Z[base+half], x2 = Z[base+2*half], x3 = Z[base+3*half];
            bf4_inv(x0, x1, x2, x3, tw[j*step], tw[j*step2]);
            Z[base] = x0; Z[base+half] = x1; Z[base+2*half] = x2; Z[base+3*half] = x3;
        }
        __syncthreads();
    }
    {
        #pragma unroll
        for (int it = 0; it < 8192/NT; it++) {
            int g = tid + it*NT;
            int row = g >> 6, j = g & 63;
            int i0 = row*ZS + j, i1 = i0 + 64;
            float2 u = Z[i0], x = Z[i1];
            float2 v = cmulc(x, tw[j]);
            Z[i0] = make_float2(u.x+v.x, u.y+v.y);
            Z[i1] = make_float2(u.x-v.x, u.y-v.y);
        }
        __syncthreads();
    }

    // extract Re (ortho 1/128), add depthwise 3x3 conv from g_xt, store
    const float sc = 1.0f/128.0f;
    #pragma unroll
    for (int it = 0; it < HWn/NT; it++) {
        int i = tid + it*NT;
        int h = i >> 7, w = i & 127;
        float v = Z[h*ZS + w].x * sc;
        float cacc = 0.f;
        #pragma unroll
        for (int dy = -1; dy <= 1; dy++) {
            #pragma unroll
            for (int dx = -1; dx <= 1; dx++) {
                int hh = h+dy, ww = w+dx;
                if (hh >= 0 && hh < Hn && ww >= 0 && ww < Wn)
                    cacc += cw[(dy+1)*3 + (dx+1)] * g_xt[(size_t)bc*HWn + hh*Wn + ww];
            }
        }
        g_spec[(size_t)bc*HWn + i] = v + cacc;
    }
}

// ---------------- K4: pointwise GEMM (FFMA2) + spec add + conditional LN ------
#define XS_STRIDE 66   // floats; 264B rows keep pixel-pairs 8B-aligned
__global__ void k4_final(const float* __restrict__ x,   const float* __restrict__ lin_b,
                         const float* __restrict__ tme,
                         const float* __restrict__ nww, const float* __restrict__ nwb,
                         const float* __restrict__ nbw, const float* __restrict__ nbb,
                         float* __restrict__ out) {
    extern __shared__ float sm[];
    float* xs  = sm;                       // [256][XS_STRIDE] x transposed: [c][pixel]
    float* ss  = sm + Cn*XS_STRIDE;        // [256][65] spec
    float* wsm = ss + Cn*65;               // [32][256] weight chunk
    int tid = threadIdx.x;
    int b  = blockIdx.x >> 8;
    int p0 = (blockIdx.x & 255) << 6;

    for (int i = tid; i < 64*Cn; i += 256) {
        int pi = i >> 8, c = i & 255;
        xs[c*XS_STRIDE + pi] = x[((size_t)b*HWn + p0 + pi)*Cn + c];
    }
    for (int i = tid; i < Cn*64; i += 256) {
        int c = i >> 6, pi = i & 63;
        ss[c*65 + pi] = g_spec[((size_t)(b*Cn + c))*HWn + p0 + pi];
    }
    __syncthreads();

    int tc = tid & 31, tp = tid >> 5;
    u64 acc2[8][4];
    #pragma unroll
    for (int q = 0; q < 8; q++) {
        int cq = tc + 32*q;
        float lb = lin_b[cq];
        #pragma unroll
        for (int rp = 0; rp < 4; rp++)
            acc2[q][rp] = pk2(lb + ss[cq*65 + tp*8 + 2*rp],
                              lb + ss[cq*65 + tp*8 + 2*rp + 1]);
    }

    for (int d0 = 0; d0 < Cn; d0 += 32) {
        __syncthreads();
        for (int i = tid; i < 32*Cn; i += 256)
            wsm[i] = g_lwT[(size_t)d0*Cn + i];
        __syncthreads();
        #pragma unroll 4
        for (int dd = 0; dd < 32; dd++) {
            int d = d0 + dd;
            const u64* xp = (const u64*)&xs[d*XS_STRIDE + tp*8];
            u64 xv2[4];
            #pragma unroll
            for (int rp = 0; rp < 4; rp++) xv2[rp] = xp[rp];
            #pragma unroll
            for (int q = 0; q < 8; q++) {
                float wv = wsm[dd*Cn + tc + 32*q];
                u64 w2 = pk2(wv, wv);
                #pragma unroll
                for (int rp = 0; rp < 4; rp++)
                    FMA2(acc2[q][rp], w2, xv2[rp], acc2[q][rp]);
            }
        }
    }

    float acc8[8][8];
    #pragma unroll
    for (int q = 0; q < 8; q++)
        #pragma unroll
        for (int rp = 0; rp < 4; rp++) {
            float2 v = upk2(acc2[q][rp]);
            acc8[q][2*rp]   = v.x;
            acc8[q][2*rp+1] = v.y;
        }

    float psum[8], psq[8];
    #pragma unroll
    for (int r = 0; r < 8; r++) { psum[r] = 0.f; psq[r] = 0.f; }
    #pragma unroll
    for (int q = 0; q < 8; q++)
        #pragma unroll
        for (int r = 0; r < 8; r++) {
            psum[r] += acc8[q][r];
            psq[r]  += acc8[q][r]*acc8[q][r];
        }
    #pragma unroll
    for (int off = 16; off > 0; off >>= 1)
        #pragma unroll
        for (int r = 0; r < 8; r++) {
            psum[r] += __shfl_xor_sync(0xffffffffu, psum[r], off);
            psq[r]  += __shfl_xor_sync(0xffffffffu, psq[r],  off);
        }
    float mean[8], rstd[8];
    #pragma unroll
    for (int r = 0; r < 8; r++) {
        mean[r] = psum[r] * (1.0f/256.0f);
        float var = psq[r] * (1.0f/256.0f) - mean[r]*mean[r];
        rstd[r] = rsqrtf(var + 1e-5f);
    }
    float t = tme[b];
    #pragma unroll
    for (int q = 0; q < 8; q++) {
        int cq = tc + 32*q;
        float wc = t * nww[cq] + nwb[cq];
        float bc_ = t * nbw[cq] + nbb[cq];
        #pragma unroll
        for (int r = 0; r < 8; r++) {
            int pi = tp*8 + r;
            out[((size_t)(b*HWn + p0 + pi))*Cn + cq] =
                wc * (acc8[q][r] - mean[r]) * rstd[r] + bc_;
        }
    }
}

// ------------------------------- launch ---------------------------------------
extern "C" void kernel_launch(void* const* d_in, const int* in_sizes, int n_in,
                              void* d_out, int out_size) {
    const float* x      = (const float*)d_in[0];
    const float* tme    = (const float*)d_in[1];
    const float* w_real = (const float*)d_in[2];
    const float* w_imag = (const float*)d_in[3];
    const float* conv_w = (const float*)d_in[4];
    const float* lin_w  = (const float*)d_in[5];
    const float* lin_b  = (const float*)d_in[6];
    const float* mlp_w1 = (const float*)d_in[7];
    const float* mlp_b1 = (const float*)d_in[8];
    const float* mlp_w2 = (const float*)d_in[9];
    const float* mlp_b2 = (const float*)d_in[10];
    const float* nww    = (const float*)d_in[11];
    const float* nwb    = (const float*)d_in[12];
    const float* nbw    = (const float*)d_in[13];
    const float* nbb    = (const float*)d_in[14];
    const float* kx     = (const float*)d_in[15];
    const float* ky     = (const float*)d_in[16];
    float* out = (float*)d_out;

    const int smem_fft = Hn*ZS*8;                                       // 134,144 B
    const int smem_k4  = (Cn*XS_STRIDE + Cn*65 + 32*Cn) * 4;            // 166,912 B
    cudaFuncSetAttribute(k1_fft,  cudaFuncAttributeMaxDynamicSharedMemorySize, smem_fft);
    cudaFuncSetAttribute(k3_ifft, cudaFuncAttributeMaxDynamicSharedMemorySize, smem_fft);
    cudaFuncSetAttribute(k4_final, cudaFuncAttributeMaxDynamicSharedMemorySize, smem_k4);

    k0_setup<<<1, 256>>>(kx, ky, lin_w);

    dim3 trg(Cn/32, HWn/32, Bn);
    k_tr<<<trg, dim3(32,8)>>>(x);

    k1_fft<<<Bn*Cn, NT, smem_fft>>>(mlp_w1, mlp_b1, mlp_w2, mlp_b2);

    dim3 mixg(Cn/32, (Bn*Fn + 31)/32);
    k2b_mix<<<mixg, 256>>>(w_real, w_imag);

    k3_ifft<<<Bn*Cn, NT, smem_fft>>>(conv_w);

    k4_final<<<Bn*(HWn/64), 256, smem_k4>>>(x, lin_b, tme, nww, nwb, nbw, nbb, out);
}

// round 10
// speedup vs baseline: 1.5753x; 1.1645x over previous
#include <cuda_runtime.h>
#include <math.h>
#include <stddef.h>

#define Bn  4
#define Cn  256
#define Hn  128
#define Wn  128
#define HWn (Hn*Wn)
#define WFn 65
#define Fn  (Hn*WFn)
#define NBn 6
#define GHn 128
#define ZS  131   // float2 row stride: 131 (8B units) ≡ 3 mod 16 -> lane=row is conflict-free
#define NT  512   // threads for FFT kernels

typedef unsigned long long u64;

// ---------------- scratch -----------------------------------------------------
__device__ float  g_xt  [Bn*Cn*HWn];
__device__ float  g_spec[Bn*Cn*HWn];
__device__ float2 g_Xf  [Bn*Cn*Fn];
__device__ float2 g_Xm  [Bn*Cn*Fn];
__device__ float  g_alpha[Bn*Cn*NBn];
__device__ float  g_lwT [Cn*Cn];
__device__ int    g_bandid[Fn];
__device__ float  g_binv[NBn];
__device__ int    g_kxi, g_kyi;

__device__ __forceinline__ int brev7(int i) { return (int)(__brev((unsigned)i) >> 25); }

__device__ __forceinline__ float2 cmul(float2 a, float2 w) {
    return make_float2(a.x*w.x - a.y*w.y, a.x*w.y + a.y*w.x);
}
__device__ __forceinline__ float2 cmulc(float2 a, float2 w) {   // a * conj(w)
    return make_float2(a.x*w.x + a.y*w.y, a.y*w.x - a.x*w.y);
}

// radix-2^2: two radix-2 stages (s, s+1) in registers.
__device__ __forceinline__ void bf4_fwd(float2& x0, float2& x1, float2& x2, float2& x3,
                                        float2 w1, float2 wA) {
    float2 wB = make_float2(wA.y, -wA.x);
    float2 v1 = cmul(x1, w1), v3 = cmul(x3, w1);
    float2 a0 = make_float2(x0.x+v1.x, x0.y+v1.y);
    float2 a1 = make_float2(x0.x-v1.x, x0.y-v1.y);
    float2 a2 = make_float2(x2.x+v3.x, x2.y+v3.y);
    float2 a3 = make_float2(x2.x-v3.x, x2.y-v3.y);
    float2 v2 = cmul(a2, wA), v4 = cmul(a3, wB);
    x0 = make_float2(a0.x+v2.x, a0.y+v2.y);
    x2 = make_float2(a0.x-v2.x, a0.y-v2.y);
    x1 = make_float2(a1.x+v4.x, a1.y+v4.y);
    x3 = make_float2(a1.x-v4.x, a1.y-v4.y);
}
__device__ __forceinline__ void bf4_inv(float2& x0, float2& x1, float2& x2, float2& x3,
                                        float2 w1, float2 wA) {
    float2 wB = make_float2(wA.y, -wA.x);
    float2 v1 = cmulc(x1, w1), v3 = cmulc(x3, w1);
    float2 a0 = make_float2(x0.x+v1.x, x0.y+v1.y);
    float2 a1 = make_float2(x0.x-v1.x, x0.y-v1.y);
    float2 a2 = make_float2(x2.x+v3.x, x2.y+v3.y);
    float2 a3 = make_float2(x2.x-v3.x, x2.y-v3.y);
    float2 v2 = cmulc(a2, wA), v4 = cmulc(a3, wB);
    x0 = make_float2(a0.x+v2.x, a0.y+v2.y);
    x2 = make_float2(a0.x-v2.x, a0.y-v2.y);
    x1 = make_float2(a1.x+v4.x, a1.y+v4.y);
    x3 = make_float2(a1.x-v4.x, a1.y-v4.y);
}

// packed f32x2 helpers (FFMA2 path)
__device__ __forceinline__ u64 pk2(float lo, float hi) {
    u64 r; asm("mov.b64 %0, {%1,%2};" : "=l"(r) : "f"(lo), "f"(hi)); return r;
}
__device__ __forceinline__ float2 upk2(u64 v) {
    float lo, hi; asm("mov.b64 {%0,%1}, %2;" : "=f"(lo), "=f"(hi) : "l"(v));
    return make_float2(lo, hi);
}
#define FMA2(d, a, b, c) asm("fma.rn.f32x2 %0, %1, %2, %3;" : "=l"(d) : "l"(a), "l"(b), "l"(c))

// ---------------- K0a: band table + mask extents (1 small block) --------------
__global__ void k0_bands(const float* __restrict__ kx, const float* __restrict__ ky) {
    __shared__ float cnt[NBn];
    int tid = threadIdx.x;
    if (tid < NBn) cnt[tid] = 0.f;
    __syncthreads();
    for (int f = tid; f < Fn; f += blockDim.x) {
        int hy = f / WFn, wx = f % WFn;
        float yy = __fdiv_rn((float)hy, 127.0f);
        float xx = __fdiv_rn((float)wx, 64.0f);
        float r  = __fsqrt_rn(__fadd_rn(__fmul_rn(yy,yy), __fmul_rn(xx,xx)));
        float rmax = __fadd_rn(__fsqrt_rn(2.0f), 1e-8f);
        float rn = __fdiv_rn(r, rmax);
        int bid = (int)floorf(__fmul_rn(rn, 6.0f));
        if (bid > NBn-1) bid = NBn-1;
        g_bandid[f] = bid;
        atomicAdd(&cnt[bid], 1.0f);
    }
    __syncthreads();
    if (tid < NBn) g_binv[tid] = 1.0f / (fmaxf(cnt[tid], 1.0f) + 1e-6f);
    if (tid == 0) {
        float sx = 1.0f / (1.0f + expf(-kx[0]));
        float sy = 1.0f / (1.0f + expf(-ky[0]));
        g_kxi = (int)floorf(sx * (float)Hn);
        g_kyi = (int)floorf(sy * (float)WFn);
    }
}

// ---------------- K0b: lin_w transpose (tiled, multi-block) -------------------
__global__ void k_trw(const float* __restrict__ lin_w) {
    __shared__ float tile[32][33];
    int c0 = blockIdx.x * 32, d0 = blockIdx.y * 32;
    int tx = threadIdx.x, ty = threadIdx.y;   // 32x8
    #pragma unroll
    for (int k = 0; k < 32; k += 8)
        tile[ty+k][tx] = lin_w[(c0+ty+k)*Cn + d0+tx];
    __syncthreads();
    #pragma unroll
    for (int k = 0; k < 32; k += 8)
        g_lwT[(d0+ty+k)*Cn + c0+tx] = tile[tx][ty+k];
}

// ---------------- K_tr: (b,p,c) -> (b,c,p) ------------------------------------
__global__ void k_tr(const float* __restrict__ x) {
    __shared__ float tile[32][33];
    int b  = blockIdx.z;
    int c0 = blockIdx.x * 32, p0 = blockIdx.y * 32;
    int tx = threadIdx.x, ty = threadIdx.y;
    #pragma unroll
    for (int k = 0; k < 32; k += 8)
        tile[ty+k][tx] = x[((size_t)b*HWn + p0+ty+k)*Cn + c0+tx];
    __syncthreads();
    #pragma unroll
    for (int k = 0; k < 32; k += 8)
        g_xt[((size_t)b*Cn + c0+ty+k)*HWn + p0+tx] = tile[tx][ty+k];
}

// ---------------- K1: forward rfft2 + fused band gate -------------------------
__global__ void __launch_bounds__(NT)
k1_fft(const float* __restrict__ w1p, const float* __restrict__ b1,
       const float* __restrict__ w2p, const float* __restrict__ b2) {
    extern __shared__ float2 Z[];          // [128][ZS]
    __shared__ float2 tw[64];
    __shared__ float  bsum[NBn];
    __shared__ float  m6[NBn];
    __shared__ float  hbuf[GHn];
    int tid = threadIdx.x;
    int bc = blockIdx.x;

    if (tid < 64) {
        float ang = -2.0f*3.14159265358979323846f*(float)tid/128.0f;
        float s, c; sincosf(ang, &s, &c);
        tw[tid] = make_float2(c, s);
    }
    if (tid < NBn) bsum[tid] = 0.f;
    // linear load (conflict-free)
    #pragma unroll
    for (int it = 0; it < HWn/NT; it++) {
        int i = tid + it*NT;
        Z[(i>>7)*ZS + (i&127)] = make_float2(g_xt[(size_t)bc*HWn + i], 0.f);
    }
    __syncthreads();

    // row bit-reverse swap pass: lane = row (stride ZS -> conflict-free)
    #pragma unroll
    for (int it = 0; it < (128*128)/NT; it++) {
        int g = tid + it*NT;
        int row = g & 127, i = g >> 7;
        int j = brev7(i);
        if (j > i) {
            float2 t = Z[row*ZS+i]; Z[row*ZS+i] = Z[row*ZS+j]; Z[row*ZS+j] = t;
        }
    }
    __syncthreads();

    // row FFTs, fused pairs: lane = row, t = g>>7 selects butterfly group
    #pragma unroll
    for (int s = 1; s <= 5; s += 2) {
        int half = 1 << (s-1), step = 128 >> s, step2 = step >> 1;
        #pragma unroll
        for (int it = 0; it < 4096/NT; it++) {
            int g = tid + it*NT;
            int row = g & 127, t = g >> 7;
            int j = t & (half-1);
            int base = row*ZS + (((t >> (s-1)) << (s+1)) + j);
            float2 x0 = Z[base], x1 = Z[base+half], x2 = Z[base+2*half], x3 = Z[base+3*half];
            bf4_fwd(x0, x1, x2, x3, tw[j*step], tw[j*step2]);
            Z[base] = x0; Z[base+half] = x1; Z[base+2*half] = x2; Z[base+3*half] = x3;
        }
        __syncthreads();
    }
    {   // row stage 7: lane = row
        #pragma unroll
        for (int it = 0; it < 8192/NT; it++) {
            int g = tid + it*NT;
            int row = g & 127, j = g >> 7;
            int i0 = row*ZS + j, i1 = i0 + 64;
            float2 u = Z[i0], x = Z[i1];
            float2 v = cmul(x, tw[j]);
            Z[i0] = make_float2(u.x+v.x, u.y+v.y);
            Z[i1] = make_float2(u.x-v.x, u.y-v.y);
        }
        __syncthreads();
    }

    // column bit-reverse (lane = col, stride 1 -> fine)
    #pragma unroll
    for (int it = 0; it < (WFn*128 + NT-1)/NT; it++) {
        int g = tid + it*NT;
        if (g < WFn*128) {
            int i = g / WFn, col = g % WFn;
            int j = brev7(i);
            if (j > i) {
                float2 t = Z[i*ZS+col]; Z[i*ZS+col] = Z[j*ZS+col]; Z[j*ZS+col] = t;
            }
        }
    }
    __syncthreads();
    // column FFTs, fused pairs (lane = col)
    #pragma unroll
    for (int s = 1; s <= 5; s += 2) {
        int half = 1 << (s-1), step = 128 >> s, step2 = step >> 1;
        #pragma unroll
        for (int it = 0; it < (2080 + NT-1)/NT; it++) {
            int g = tid + it*NT;
            if (g < 2080) {
                int col = g % WFn, t = g / WFn;
                int j = t & (half-1);
                int base = (((t >> (s-1)) << (s+1)) + j)*ZS + col;
                int hs = half*ZS;
                float2 x0 = Z[base], x1 = Z[base+hs], x2 = Z[base+2*hs], x3 = Z[base+3*hs];
                bf4_fwd(x0, x1, x2, x3, tw[j*step], tw[j*step2]);
                Z[base] = x0; Z[base+hs] = x1; Z[base+2*hs] = x2; Z[base+3*hs] = x3;
            }
        }
        __syncthreads();
    }
    {   // column stage 7
        #pragma unroll
        for (int it = 0; it < (4160 + NT-1)/NT; it++) {
            int g = tid + it*NT;
            if (g < 4160) {
                int col = g % WFn, j = g / WFn;
                int i0 = j*ZS + col, i1 = i0 + 64*ZS;
                float2 u = Z[i0], x = Z[i1];
                float2 v = cmul(x, tw[j]);
                Z[i0] = make_float2(u.x+v.x, u.y+v.y);
                Z[i1] = make_float2(u.x-v.x, u.y-v.y);
            }
        }
        __syncthreads();
    }

    // store spectrum (ortho scale) + per-band |Xf| sums
    const float sc = 1.0f/128.0f;
    float s6[NBn];
    #pragma unroll
    for (int n = 0; n < NBn; n++) s6[n] = 0.f;
    #pragma unroll
    for (int it = 0; it < (Fn + NT-1)/NT; it++) {
        int i = tid + it*NT;
        if (i < Fn) {
            int h = i / WFn, k = i - h*WFn;
            float2 v = Z[h*ZS + k];
            v.x *= sc; v.y *= sc;
            g_Xf[(size_t)bc*Fn + i] = v;
            float mag = sqrtf(v.x*v.x + v.y*v.y);
            int bid = g_bandid[i];
            #pragma unroll
            for (int n = 0; n < NBn; n++) s6[n] += (bid == n) ? mag : 0.f;
        }
    }
    #pragma unroll
    for (int off = 16; off > 0; off >>= 1)
        #pragma unroll
        for (int n = 0; n < NBn; n++)
            s6[n] += __shfl_xor_sync(0xffffffffu, s6[n], off);
    if ((tid & 31) == 0)
        #pragma unroll
        for (int n = 0; n < NBn; n++) atomicAdd(&bsum[n], s6[n]);
    __syncthreads();

    if (tid < NBn) m6[tid] = bsum[tid] * g_binv[tid];
    __syncthreads();
    if (tid < GHn) {
        float acc = b1[tid];
        #pragma unroll
        for (int n = 0; n < NBn; n++) acc += m6[n] * w1p[tid*NBn + n];
        hbuf[tid] = fmaxf(acc, 0.f);
    }
    __syncthreads();
    if (tid < NBn) {
        float acc = b2[tid];
        for (int j = 0; j < GHn; j++) acc += hbuf[j] * w2p[tid*GHn + j];
        g_alpha[bc*NBn + tid] = 1.0f / (1.0f + expf(-acc));
    }
}

// ---------------- K2b: complex channel-mix GEMM over masked freqs -------------
__global__ void k2b_mix(const float* __restrict__ wr, const float* __restrict__ wi) {
    __shared__ float2 Wt[32*16];
    __shared__ float2 Xt[16*32];
    __shared__ int    ibase[32];
    __shared__ int    okf[32];
    int kxi = g_kxi, kyi = g_kyi;
    int maskcnt = kxi * kyi;
    int Ntot = Bn * maskcnt;
    int n0 = blockIdx.y * 32;
    if (n0 >= Ntot) return;
    int c0 = blockIdx.x * 32;
    int tid = threadIdx.x;
    int tx = tid & 31, ty = tid >> 5;
    if (tid < 32) {
        int n = n0 + tid;
        if (n < Ntot) {
            int b = n / maskcnt, m = n % maskcnt;
            int hy = m / kyi, wx = m % kyi;
            ibase[tid] = b*Cn*Fn + hy*WFn + wx;
            okf[tid] = 1;
        } else { ibase[tid] = 0; okf[tid] = 0; }
    }
    __syncthreads();
    float2 acc[4];
    #pragma unroll
    for (int q = 0; q < 4; q++) acc[q] = make_float2(0.f, 0.f);
    for (int d0 = 0; d0 < Cn; d0 += 16) {
        #pragma unroll
        for (int i0 = 0; i0 < 2; i0++) {
            int i = tid + i0*256;
            int cc = i >> 4, dd = i & 15;
            int gi = (c0+cc)*Cn + d0+dd;
            Wt[i] = make_float2(wr[gi], wi[gi]);
        }
        #pragma unroll
        for (int i0 = 0; i0 < 2; i0++) {
            int i = tid + i0*256;
            int dd = i >> 5, j = i & 31;
            Xt[i] = okf[j] ? g_Xf[(size_t)ibase[j] + (size_t)(d0+dd)*Fn]
                           : make_float2(0.f, 0.f);
        }
        __syncthreads();
        #pragma unroll
        for (int dd = 0; dd < 16; dd++) {
            float2 xv = Xt[dd*32 + tx];
            #pragma unroll
            for (int q = 0; q < 4; q++) {
                float2 wv = Wt[(ty + 8*q)*16 + dd];
                acc[q].x += wv.x*xv.x - wv.y*xv.y;
                acc[q].y += wv.x*xv.y + wv.y*xv.x;
            }
        }
        __syncthreads();
    }
    if (okf[tx]) {
        int n = n0 + tx;
        int b = n / maskcnt;
        int f = ibase[tx] - b*Cn*Fn;
        #pragma unroll
        for (int q = 0; q < 4; q++)
            g_Xm[((size_t)(b*Cn + c0 + ty + 8*q))*Fn + f] = acc[q];
    }
}

// ---------------- K3: gated spectrum -> irfft2 (+ depthwise conv) -------------
__global__ void __launch_bounds__(NT)
k3_ifft(const float* __restrict__ conv_w) {
    extern __shared__ float2 Z[];          // [128][ZS]
    __shared__ float2 tw[64];
    __shared__ float  a6[NBn];
    __shared__ float  cw[9];
    int tid = threadIdx.x;
    int bc = blockIdx.x;
    int c  = bc & (Cn-1);

    if (tid < 64) {
        float ang = -2.0f*3.14159265358979323846f*(float)tid/128.0f;
        float s_, c_; sincosf(ang, &s_, &c_);
        tw[tid] = make_float2(c_, s_);     // forward twiddles; conj at use
    }
    if (tid < NBn) a6[tid] = g_alpha[bc*NBn + tid];
    if (tid < 9)   cw[tid] = conv_w[c*9 + tid];
    int kxi = g_kxi, kyi = g_kyi;
    __syncthreads();

    // fused gated spectrum into cols 0..64
    #pragma unroll
    for (int it = 0; it < (Fn + NT-1)/NT; it++) {
        int i = tid + it*NT;
        if (i < Fn) {
            int h = i / WFn, k = i - h*WFn;
            float al = a6[g_bandid[i]];
            float2 z;
            if (h < kxi && k < kyi) {
                z = g_Xm[(size_t)bc*Fn + i];
                z.x *= al; z.y *= al;
            } else {
                z = g_Xf[(size_t)bc*Fn + i];
                float om = 1.0f - al;
                z.x *= om; z.y *= om;
            }
            Z[h*ZS + k] = z;
        }
    }
    __syncthreads();

    // inverse column FFTs (lane = col)
    #pragma unroll
    for (int it = 0; it < (WFn*128 + NT-1)/NT; it++) {
        int g = tid + it*NT;
        if (g < WFn*128) {
            int i = g / WFn, col = g % WFn;
            int j = brev7(i);
            if (j > i) {
                float2 t = Z[i*ZS+col]; Z[i*ZS+col] = Z[j*ZS+col]; Z[j*ZS+col] = t;
            }
        }
    }
    __syncthreads();
    #pragma unroll
    for (int s = 1; s <= 5; s += 2) {
        int half = 1 << (s-1), step = 128 >> s, step2 = step >> 1;
        #pragma unroll
        for (int it = 0; it < (2080 + NT-1)/NT; it++) {
            int g = tid + it*NT;
            if (g < 2080) {
                int col = g % WFn, t = g / WFn;
                int j = t & (half-1);
                int base = (((t >> (s-1)) << (s+1)) + j)*ZS + col;
                int hs = half*ZS;
                float2 x0 = Z[base], x1 = Z[base+hs], x2 = Z[base+2*hs], x3 = Z[base+3*hs];
                bf4_inv(x0, x1, x2, x3, tw[j*step], tw[j*step2]);
                Z[base] = x0; Z[base+hs] = x1; Z[base+2*hs] = x2; Z[base+3*hs] = x3;
            }
        }
        __syncthreads();
    }
    {
        #pragma unroll
        for (int it = 0; it < (4160 + NT-1)/NT; it++) {
            int g = tid + it*NT;
            if (g < 4160) {
                int col = g % WFn, j = g / WFn;
                int i0 = j*ZS + col, i1 = i0 + 64*ZS;
                float2 u = Z[i0], x = Z[i1];
                float2 v = cmulc(x, tw[j]);
                Z[i0] = make_float2(u.x+v.x, u.y+v.y);
                Z[i1] = make_float2(u.x-v.x, u.y-v.y);
            }
        }
        __syncthreads();
    }

    // hermitian mirror each row: cols 65..127 = conj(cols 63..1).
    #pragma unroll
    for (int it = 0; it < (128*63 + NT-1)/NT; it++) {
        int g = tid + it*NT;
        if (g < 128*63) {
            int h = g / 63, k = 65 + (g % 63);
            float2 v = Z[h*ZS + (128 - k)];
            Z[h*ZS + k] = make_float2(v.x, -v.y);
        }
    }
    __syncthreads();

    // inverse row FFTs: swap pass + butterflies with lane = row
    #pragma unroll
    for (int it = 0; it < (128*128)/NT; it++) {
        int g = tid + it*NT;
        int row = g & 127, i = g >> 7;
        int j = brev7(i);
        if (j > i) {
            float2 t = Z[row*ZS+i]; Z[row*ZS+i] = Z[row*ZS+j]; Z[row*ZS+j] = t;
        }
    }
    __syncthreads();
    #pragma unroll
    for (int s = 1; s <= 5; s += 2) {
        int half = 1 << (s-1), step = 128 >> s, step2 = step >> 1;
        #pragma unroll
        for (int it = 0; it < 4096/NT; it++) {
            int g = tid + it*NT;
            int row = g & 127, t = g >> 7;
            int j = t & (half-1);
            int base = row*ZS + (((t >> (s-1)) << (s+1)) + j);
            float2 x0 = Z[base], x1 = Z[base+half], x2 = Z[base+2*half], x3 = Z[base+3*half];
            bf4_inv(x0, x1, x2, x3, tw[j*step], tw[j*step2]);
            Z[base] = x0; Z[base+half] = x1; Z[base+2*half] = x2; Z[base+3*half] = x3;
        }
        __syncthreads();
    }
    {
        #pragma unroll
        for (int it = 0; it < 8192/NT; it++) {
            int g = tid + it*NT;
            int row = g & 127, j = g >> 7;
            int i0 = row*ZS + j, i1 = i0 + 64;
            float2 u = Z[i0], x = Z[i1];
            float2 v = cmulc(x, tw[j]);
            Z[i0] = make_float2(u.x+v.x, u.y+v.y);
            Z[i1] = make_float2(u.x-v.x, u.y-v.y);
        }
        __syncthreads();
    }

    // extract Re (ortho 1/128), add depthwise 3x3 conv from g_xt, store
    const float sc = 1.0f/128.0f;
    #pragma unroll
    for (int it = 0; it < HWn/NT; it++) {
        int i = tid + it*NT;
        int h = i >> 7, w = i & 127;
        float v = Z[h*ZS + w].x * sc;
        float cacc = 0.f;
        #pragma unroll
        for (int dy = -1; dy <= 1; dy++) {
            #pragma unroll
            for (int dx = -1; dx <= 1; dx++) {
                int hh = h+dy, ww = w+dx;
                if (hh >= 0 && hh < Hn && ww >= 0 && ww < Wn)
                    cacc += cw[(dy+1)*3 + (dx+1)] * g_xt[(size_t)bc*HWn + hh*Wn + ww];
            }
        }
        g_spec[(size_t)bc*HWn + i] = v + cacc;
    }
}

// ---------------- K4: pointwise GEMM (FFMA2) + spec add + conditional LN ------
#define XS_STRIDE 66
__global__ void k4_final(const float* __restrict__ x,   const float* __restrict__ lin_b,
                         const float* __restrict__ tme,
                         const float* __restrict__ nww, const float* __restrict__ nwb,
                         const float* __restrict__ nbw, const float* __restrict__ nbb,
                         float* __restrict__ out) {
    extern __shared__ float sm[];
    float* xs  = sm;                       // [256][XS_STRIDE]
    float* ss  = sm + Cn*XS_STRIDE;        // [256][65]
    float* wsm = ss + Cn*65;               // [32][256]
    int tid = threadIdx.x;
    int b  = blockIdx.x >> 8;
    int p0 = (blockIdx.x & 255) << 6;

    for (int i = tid; i < 64*Cn; i += 256) {
        int pi = i >> 8, c = i & 255;
        xs[c*XS_STRIDE + pi] = x[((size_t)b*HWn + p0 + pi)*Cn + c];
    }
    for (int i = tid; i < Cn*64; i += 256) {
        int c = i >> 6, pi = i & 63;
        ss[c*65 + pi] = g_spec[((size_t)(b*Cn + c))*HWn + p0 + pi];
    }
    __syncthreads();

    int tc = tid & 31, tp = tid >> 5;
    u64 acc2[8][4];
    #pragma unroll
    for (int q = 0; q < 8; q++) {
        int cq = tc + 32*q;
        float lb = lin_b[cq];
        #pragma unroll
        for (int rp = 0; rp < 4; rp++)
            acc2[q][rp] = pk2(lb + ss[cq*65 + tp*8 + 2*rp],
                              lb + ss[cq*65 + tp*8 + 2*rp + 1]);
    }

    for (int d0 = 0; d0 < Cn; d0 += 32) {
        __syncthreads();
        for (int i = tid; i < 32*Cn; i += 256)
            wsm[i] = g_lwT[(size_t)d0*Cn + i];
        __syncthreads();
        #pragma unroll 4
        for (int dd = 0; dd < 32; dd++) {
            int d = d0 + dd;
            const u64* xp = (const u64*)&xs[d*XS_STRIDE + tp*8];
            u64 xv2[4];
            #pragma unroll
            for (int rp = 0; rp < 4; rp++) xv2[rp] = xp[rp];
            #pragma unroll
            for (int q = 0; q < 8; q++) {
                float wv = wsm[dd*Cn + tc + 32*q];
                u64 w2 = pk2(wv, wv);
                #pragma unroll
                for (int rp = 0; rp < 4; rp++)
                    FMA2(acc2[q][rp], w2, xv2[rp], acc2[q][rp]);
            }
        }
    }

    float acc8[8][8];
    #pragma unroll
    for (int q = 0; q < 8; q++)
        #pragma unroll
        for (int rp = 0; rp < 4; rp++) {
            float2 v = upk2(acc2[q][rp]);
            acc8[q][2*rp]   = v.x;
            acc8[q][2*rp+1] = v.y;
        }

    float psum[8], psq[8];
    #pragma unroll
    for (int r = 0; r < 8; r++) { psum[r] = 0.f; psq[r] = 0.f; }
    #pragma unroll
    for (int q = 0; q < 8; q++)
        #pragma unroll
        for (int r = 0; r < 8; r++) {
            psum[r] += acc8[q][r];
            psq[r]  += acc8[q][r]*acc8[q][r];
        }
    #pragma unroll
    for (int off = 16; off > 0; off >>= 1)
        #pragma unroll
        for (int r = 0; r < 8; r++) {
            psum[r] += __shfl_xor_sync(0xffffffffu, psum[r], off);
            psq[r]  += __shfl_xor_sync(0xffffffffu, psq[r],  off);
        }
    float mean[8], rstd[8];
    #pragma unroll
    for (int r = 0; r < 8; r++) {
        mean[r] = psum[r] * (1.0f/256.0f);
        float var = psq[r] * (1.0f/256.0f) - mean[r]*mean[r];
        rstd[r] = rsqrtf(var + 1e-5f);
    }
    float t = tme[b];
    #pragma unroll
    for (int q = 0; q < 8; q++) {
        int cq = tc + 32*q;
        float wc = t * nww[cq] + nwb[cq];
        float bc_ = t * nbw[cq] + nbb[cq];
        #pragma unroll
        for (int r = 0; r < 8; r++) {
            int pi = tp*8 + r;
            out[((size_t)(b*HWn + p0 + pi))*Cn + cq] =
                wc * (acc8[q][r] - mean[r]) * rstd[r] + bc_;
        }
    }
}

// ------------------------------- launch ---------------------------------------
extern "C" void kernel_launch(void* const* d_in, const int* in_sizes, int n_in,
                              void* d_out, int out_size) {
    const float* x      = (const float*)d_in[0];
    const float* tme    = (const float*)d_in[1];
    const float* w_real = (const float*)d_in[2];
    const float* w_imag = (const float*)d_in[3];
    const float* conv_w = (const float*)d_in[4];
    const float* lin_w  = (const float*)d_in[5];
    const float* lin_b  = (const float*)d_in[6];
    const float* mlp_w1 = (const float*)d_in[7];
    const float* mlp_b1 = (const float*)d_in[8];
    const float* mlp_w2 = (const float*)d_in[9];
    const float* mlp_b2 = (const float*)d_in[10];
    const float* nww    = (const float*)d_in[11];
    const float* nwb    = (const float*)d_in[12];
    const float* nbw    = (const float*)d_in[13];
    const float* nbb    = (const float*)d_in[14];
    const float* kx     = (const float*)d_in[15];
    const float* ky     = (const float*)d_in[16];
    float* out = (float*)d_out;

    const int smem_fft = Hn*ZS*8;                                       // 134,144 B
    const int smem_k4  = (Cn*XS_STRIDE + Cn*65 + 32*Cn) * 4;            // 166,912 B
    cudaFuncSetAttribute(k1_fft,  cudaFuncAttributeMaxDynamicSharedMemorySize, smem_fft);
    cudaFuncSetAttribute(k3_ifft, cudaFuncAttributeMaxDynamicSharedMemorySize, smem_fft);
    cudaFuncSetAttribute(k4_final, cudaFuncAttributeMaxDynamicSharedMemorySize, smem_k4);

    k0_bands<<<1, 256>>>(kx, ky);
    k_trw<<<dim3(8,8), dim3(32,8)>>>(lin_w);

    dim3 trg(Cn/32, HWn/32, Bn);
    k_tr<<<trg, dim3(32,8)>>>(x);

    k1_fft<<<Bn*Cn, NT, smem_fft>>>(mlp_w1, mlp_b1, mlp_w2, mlp_b2);

    dim3 mixg(Cn/32, (Bn*Fn + 31)/32);
    k2b_mix<<<mixg, 256>>>(w_real, w_imag);

    k3_ifft<<<Bn*Cn, NT, smem_fft>>>(conv_w);

    k4_final<<<Bn*(HWn/64), 256, smem_k4>>>(x, lin_b, tme, nww, nwb, nbw, nbb, out);
}

// round 11
// speedup vs baseline: 1.8295x; 1.1614x over previous
#include <cuda_runtime.h>
#include <math.h>
#include <stddef.h>

#define Bn  4
#define Cn  256
#define Hn  128
#define Wn  128
#define HWn (Hn*Wn)
#define WFn 65
#define Fn  (Hn*WFn)     // 8320, also size of compressed spectral tile [128][65]
#define NBn 6
#define GHn 128
#define P   65           // smem float2 row stride (odd -> conflict-free column walks)
#define NT  512

typedef unsigned long long u64;

// ---------------- scratch -----------------------------------------------------
__device__ float  g_xt  [Bn*Cn*HWn];
__device__ float  g_spec[Bn*Cn*HWn];
__device__ float2 g_Xf  [Bn*Cn*Fn];    // compressed-brev layout [h][cc]
__device__ float2 g_Xm  [Bn*Cn*Fn];    // same layout (masked region valid)
__device__ float  g_alpha[Bn*Cn*NBn];
__device__ float  g_lwT [Cn*Cn];
__device__ int    g_bandid[Fn];        // band of (h, cc) in compressed layout
__device__ float  g_binv[NBn];
__device__ int    g_kxi, g_kyi;

__device__ __forceinline__ int brev7(int i) { return (int)(__brev((unsigned)i) >> 25); }

__device__ __forceinline__ float2 cmul(float2 a, float2 w) {
    return make_float2(a.x*w.x - a.y*w.y, a.x*w.y + a.y*w.x);
}
__device__ __forceinline__ float2 cadd(float2 a, float2 b){ return make_float2(a.x+b.x, a.y+b.y); }
__device__ __forceinline__ float2 csub(float2 a, float2 b){ return make_float2(a.x-b.x, a.y-b.y); }
__device__ __forceinline__ float2 shflx(float2 v, int m) {
    return make_float2(__shfl_xor_sync(0xffffffffu, v.x, m),
                       __shfl_xor_sync(0xffffffffu, v.y, m));
}

// per-lane twiddles (direction baked into the tw table)
struct LaneTw { float2 t128a, t128b, t64, t32, t16, t8, t4; };

__device__ __forceinline__ LaneTw load_lane_tw(const float2* tw, int l) {
    LaneTw T;
    T.t128a = tw[l];
    T.t128b = cmul(tw[l], tw[32]);   // W^(l+32) = W^l * W^32 (works fwd & conj)
    T.t64 = tw[2*l];
    T.t32 = tw[4*(l&15)];
    T.t16 = tw[8*(l&7)];
    T.t8  = tw[16*(l&3)];
    T.t4  = tw[32*(l&1)];
    return T;
}

// DIF-128: natural input (position n = 32q+l), output: position n holds X[brev7(n)]
__device__ __forceinline__ void fft128_dif(float2& x0, float2& x1, float2& x2, float2& x3,
                                           const LaneTw& T, int l) {
    { float2 u=x0, v=x2; x0=cadd(u,v); x2=cmul(csub(u,v), T.t128a);     // stride 64
      u=x1; v=x3;        x1=cadd(u,v); x3=cmul(csub(u,v), T.t128b); }
    { float2 u=x0, v=x1; x0=cadd(u,v); x1=cmul(csub(u,v), T.t64);       // stride 32
      u=x2; v=x3;        x2=cadd(u,v); x3=cmul(csub(u,v), T.t64); }
#define DIF_STAGE(mask, twv) { float2 p; \
    p = shflx(x0, mask); x0 = (l & mask) ? cmul(csub(p,x0), twv) : cadd(x0,p); \
    p = shflx(x1, mask); x1 = (l & mask) ? cmul(csub(p,x1), twv) : cadd(x1,p); \
    p = shflx(x2, mask); x2 = (l & mask) ? cmul(csub(p,x2), twv) : cadd(x2,p); \
    p = shflx(x3, mask); x3 = (l & mask) ? cmul(csub(p,x3), twv) : cadd(x3,p); }
    DIF_STAGE(16, T.t32)
    DIF_STAGE(8,  T.t16)
    DIF_STAGE(4,  T.t8)
    DIF_STAGE(2,  T.t4)
#undef DIF_STAGE
    { float2 p;                                                          // stride 1 (W=1)
      p = shflx(x0,1); x0 = (l&1) ? csub(p,x0) : cadd(x0,p);
      p = shflx(x1,1); x1 = (l&1) ? csub(p,x1) : cadd(x1,p);
      p = shflx(x2,1); x2 = (l&1) ? csub(p,x2) : cadd(x2,p);
      p = shflx(x3,1); x3 = (l&1) ? csub(p,x3) : cadd(x3,p); }
}

// DIT-128: input position n holds x[brev7(n)], output: position n holds X[n]
__device__ __forceinline__ void fft128_dit(float2& x0, float2& x1, float2& x2, float2& x3,
                                           const LaneTw& T, int l) {
    { float2 p;                                                          // stride 1 (W=1)
      p = shflx(x0,1); x0 = (l&1) ? csub(p,x0) : cadd(x0,p);
      p = shflx(x1,1); x1 = (l&1) ? csub(p,x1) : cadd(x1,p);
      p = shflx(x2,1); x2 = (l&1) ? csub(p,x2) : cadd(x2,p);
      p = shflx(x3,1); x3 = (l&1) ? csub(p,x3) : cadd(x3,p); }
#define DIT_STAGE(mask, twv) { float2 p; \
    p = shflx(x0, mask); x0 = (l & mask) ? csub(p, cmul(x0,twv)) : cadd(x0, cmul(p,twv)); \
    p = shflx(x1, mask); x1 = (l & mask) ? csub(p, cmul(x1,twv)) : cadd(x1, cmul(p,twv)); \
    p = shflx(x2, mask); x2 = (l & mask) ? csub(p, cmul(x2,twv)) : cadd(x2, cmul(p,twv)); \
    p = shflx(x3, mask); x3 = (l & mask) ? csub(p, cmul(x3,twv)) : cadd(x3, cmul(p,twv)); }
    DIT_STAGE(2,  T.t4)
    DIT_STAGE(4,  T.t8)
    DIT_STAGE(8,  T.t16)
    DIT_STAGE(16, T.t32)
#undef DIT_STAGE
    { float2 v = cmul(x1, T.t64); x1 = csub(x0,v); x0 = cadd(x0,v);      // stride 32
      v = cmul(x3, T.t64);        x3 = csub(x2,v); x2 = cadd(x2,v); }
    { float2 v = cmul(x2, T.t128a); x2 = csub(x0,v); x0 = cadd(x0,v);    // stride 64
      v = cmul(x3, T.t128b);        x3 = csub(x1,v); x1 = cadd(x1,v); }
}

// packed f32x2 helpers (k4)
__device__ __forceinline__ u64 pk2(float lo, float hi) {
    u64 r; asm("mov.b64 %0, {%1,%2};" : "=l"(r) : "f"(lo), "f"(hi)); return r;
}
__device__ __forceinline__ float2 upk2(u64 v) {
    float lo, hi; asm("mov.b64 {%0,%1}, %2;" : "=f"(lo), "=f"(hi) : "l"(v));
    return make_float2(lo, hi);
}
#define FMA2(d, a, b, c) asm("fma.rn.f32x2 %0, %1, %2, %3;" : "=l"(d) : "l"(a), "l"(b), "l"(c))

// ---------------- K0a: band table (compressed layout) + mask extents ----------
__global__ void k0_bands(const float* __restrict__ kx, const float* __restrict__ ky) {
    __shared__ float cnt[NBn];
    int tid = threadIdx.x;
    if (tid < NBn) cnt[tid] = 0.f;
    __syncthreads();
    for (int f = tid; f < Fn; f += blockDim.x) {
        int hy = f / 65, cc = f % 65;
        int wx = (cc == 64) ? 64 : brev7(2*cc);       // spectral k held at this cc
        float yy = __fdiv_rn((float)hy, 127.0f);
        float xx = __fdiv_rn((float)wx, 64.0f);
        float r  = __fsqrt_rn(__fadd_rn(__fmul_rn(yy,yy), __fmul_rn(xx,xx)));
        float rmax = __fadd_rn(__fsqrt_rn(2.0f), 1e-8f);
        float rn = __fdiv_rn(r, rmax);
        int bid = (int)floorf(__fmul_rn(rn, 6.0f));
        if (bid > NBn-1) bid = NBn-1;
        g_bandid[f] = bid;
        atomicAdd(&cnt[bid], 1.0f);
    }
    __syncthreads();
    if (tid < NBn) g_binv[tid] = 1.0f / (fmaxf(cnt[tid], 1.0f) + 1e-6f);
    if (tid == 0) {
        float sx = 1.0f / (1.0f + expf(-kx[0]));
        float sy = 1.0f / (1.0f + expf(-ky[0]));
        g_kxi = (int)floorf(sx * (float)Hn);
        g_kyi = (int)floorf(sy * (float)WFn);
    }
}

// ---------------- K0b: lin_w transpose ----------------------------------------
__global__ void k_trw(const float* __restrict__ lin_w) {
    __shared__ float tile[32][33];
    int c0 = blockIdx.x * 32, d0 = blockIdx.y * 32;
    int tx = threadIdx.x, ty = threadIdx.y;
    #pragma unroll
    for (int k = 0; k < 32; k += 8)
        tile[ty+k][tx] = lin_w[(c0+ty+k)*Cn + d0+tx];
    __syncthreads();
    #pragma unroll
    for (int k = 0; k < 32; k += 8)
        g_lwT[(d0+ty+k)*Cn + c0+tx] = tile[tx][ty+k];
}

// ---------------- K_tr: (b,p,c) -> (b,c,p) ------------------------------------
__global__ void k_tr(const float* __restrict__ x) {
    __shared__ float tile[32][33];
    int b  = blockIdx.z;
    int c0 = blockIdx.x * 32, p0 = blockIdx.y * 32;
    int tx = threadIdx.x, ty = threadIdx.y;
    #pragma unroll
    for (int k = 0; k < 32; k += 8)
        tile[ty+k][tx] = x[((size_t)b*HWn + p0+ty+k)*Cn + c0+tx];
    __syncthreads();
    #pragma unroll
    for (int k = 0; k < 32; k += 8)
        g_xt[((size_t)b*Cn + c0+ty+k)*HWn + p0+tx] = tile[tx][ty+k];
}

// ---------------- K1: forward rfft2 (warp-register FFT) + fused band gate -----
__global__ void __launch_bounds__(NT, 2)
k1_fft(const float* __restrict__ w1p, const float* __restrict__ b1,
       const float* __restrict__ w2p, const float* __restrict__ b2) {
    extern __shared__ float2 Z[];          // [128][P] compressed spectral workspace
    __shared__ float2 tw[64];
    __shared__ float  bsum[NBn];
    __shared__ float  m6[NBn];
    __shared__ float  hbuf[GHn];
    int tid = threadIdx.x;
    int l = tid & 31, w = tid >> 5;
    int bc = blockIdx.x;

    if (tid < 64) {
        float ang = -2.0f*3.14159265358979323846f*(float)tid/128.0f;   // forward
        float s, c; sincosf(ang, &s, &c);
        tw[tid] = make_float2(c, s);
    }
    if (tid < NBn) bsum[tid] = 0.f;
    __syncthreads();
    LaneTw T = load_lane_tw(tw, l);

    // ---- row FFTs (DIF): natural gmem row -> compressed store at row brev7(r)
    const float* src0 = g_xt + (size_t)bc*HWn;
    #pragma unroll
    for (int i = 0; i < 8; i++) {
        int r = w + 16*i;
        const float* src = src0 + r*128;
        float2 x0 = make_float2(src[l],      0.f);
        float2 x1 = make_float2(src[32 + l], 0.f);
        float2 x2 = make_float2(src[64 + l], 0.f);
        float2 x3 = make_float2(src[96 + l], 0.f);
        fft128_dif(x0, x1, x2, x3, T, l);
        float2* zr = Z + brev7(r)*P;
        if (!(l & 1)) {                    // positions n=32q+l even -> cc = 16q + l/2
            int c0 = l >> 1;
            zr[c0]      = x0;
            zr[16 + c0] = x1;
            zr[32 + c0] = x2;
            zr[48 + c0] = x3;
        } else if (l == 1) {
            zr[64] = x0;                   // n=1 -> spectral k=64
        }
    }
    __syncthreads();

    // ---- column FFTs (DIT): smem rows are brev-ordered == DIT input; natural out
    for (int cc = w; cc < 65; cc += 16) {
        float2 x0 = Z[(l      )*P + cc];
        float2 x1 = Z[(32 + l )*P + cc];
        float2 x2 = Z[(64 + l )*P + cc];
        float2 x3 = Z[(96 + l )*P + cc];
        fft128_dit(x0, x1, x2, x3, T, l);
        Z[(l      )*P + cc] = x0;
        Z[(32 + l )*P + cc] = x1;
        Z[(64 + l )*P + cc] = x2;
        Z[(96 + l )*P + cc] = x3;
    }
    __syncthreads();

    // ---- store spectrum (ortho scale) + per-band |Xf| sums (linear: addr==index)
    const float sc = 1.0f/128.0f;
    float s6[NBn];
    #pragma unroll
    for (int n = 0; n < NBn; n++) s6[n] = 0.f;
    #pragma unroll
    for (int it = 0; it < (Fn + NT-1)/NT; it++) {
        int i = tid + it*NT;
        if (i < Fn) {
            float2 v = Z[i];
            v.x *= sc; v.y *= sc;
            g_Xf[(size_t)bc*Fn + i] = v;
            float mag = sqrtf(v.x*v.x + v.y*v.y);
            int bid = g_bandid[i];
            #pragma unroll
            for (int n = 0; n < NBn; n++) s6[n] += (bid == n) ? mag : 0.f;
        }
    }
    #pragma unroll
    for (int off = 16; off > 0; off >>= 1)
        #pragma unroll
        for (int n = 0; n < NBn; n++)
            s6[n] += __shfl_xor_sync(0xffffffffu, s6[n], off);
    if (l == 0)
        #pragma unroll
        for (int n = 0; n < NBn; n++) atomicAdd(&bsum[n], s6[n]);
    __syncthreads();

    if (tid < NBn) m6[tid] = bsum[tid] * g_binv[tid];
    __syncthreads();
    if (tid < GHn) {
        float acc = b1[tid];
        #pragma unroll
        for (int n = 0; n < NBn; n++) acc += m6[n] * w1p[tid*NBn + n];
        hbuf[tid] = fmaxf(acc, 0.f);
    }
    __syncthreads();
    if (tid < NBn) {
        float acc = b2[tid];
        for (int j = 0; j < GHn; j++) acc += hbuf[j] * w2p[tid*GHn + j];
        g_alpha[bc*NBn + tid] = 1.0f / (1.0f + expf(-acc));
    }
}

// ---------------- K2b: complex channel-mix GEMM over masked freqs -------------
__global__ void k2b_mix(const float* __restrict__ wr, const float* __restrict__ wi) {
    __shared__ float2 Wt[32*16];
    __shared__ float2 Xt[16*32];
    __shared__ int    ibase[32];
    __shared__ int    okf[32];
    int kxi = g_kxi, kyi = g_kyi;
    int maskcnt = kxi * kyi;
    int Ntot = Bn * maskcnt;
    int n0 = blockIdx.y * 32;
    if (n0 >= Ntot) return;
    int c0 = blockIdx.x * 32;
    int tid = threadIdx.x;
    int tx = tid & 31, ty = tid >> 5;
    if (tid < 32) {
        int n = n0 + tid;
        if (n < Ntot) {
            int b = n / maskcnt, m = n % maskcnt;
            int hy = m / kyi, wx = m % kyi;
            int cc = (wx == 64) ? 64 : (brev7(wx) >> 1);   // compressed col of k=wx
            ibase[tid] = b*Cn*Fn + hy*65 + cc;
            okf[tid] = 1;
        } else { ibase[tid] = 0; okf[tid] = 0; }
    }
    __syncthreads();
    float2 acc[4];
    #pragma unroll
    for (int q = 0; q < 4; q++) acc[q] = make_float2(0.f, 0.f);
    for (int d0 = 0; d0 < Cn; d0 += 16) {
        #pragma unroll
        for (int i0 = 0; i0 < 2; i0++) {
            int i = tid + i0*256;
            int cc = i >> 4, dd = i & 15;
            int gi = (c0+cc)*Cn + d0+dd;
            Wt[i] = make_float2(wr[gi], wi[gi]);
        }
        #pragma unroll
        for (int i0 = 0; i0 < 2; i0++) {
            int i = tid + i0*256;
            int dd = i >> 5, j = i & 31;
            Xt[i] = okf[j] ? g_Xf[(size_t)ibase[j] + (size_t)(d0+dd)*Fn]
                           : make_float2(0.f, 0.f);
        }
        __syncthreads();
        #pragma unroll
        for (int dd = 0; dd < 16; dd++) {
            float2 xv = Xt[dd*32 + tx];
            #pragma unroll
            for (int q = 0; q < 4; q++) {
                float2 wv = Wt[(ty + 8*q)*16 + dd];
                acc[q].x += wv.x*xv.x - wv.y*xv.y;
                acc[q].y += wv.x*xv.y + wv.y*xv.x;
            }
        }
        __syncthreads();
    }
    if (okf[tx]) {
        int n = n0 + tx;
        int b = n / maskcnt;
        int f = ibase[tx] - b*Cn*Fn;
        #pragma unroll
        for (int q = 0; q < 4; q++)
            g_Xm[((size_t)(b*Cn + c0 + ty + 8*q))*Fn + f] = acc[q];
    }
}

// ---------------- K3: gated spectrum -> irfft2 (warp-register) + conv ---------
__global__ void __launch_bounds__(NT, 2)
k3_ifft(const float* __restrict__ conv_w) {
    extern __shared__ float2 Z[];          // [128][P]
    __shared__ float2 tw[64];              // CONJUGATED twiddles (inverse)
    __shared__ float  a6[NBn];
    __shared__ float  cw[9];
    int tid = threadIdx.x;
    int l = tid & 31, w = tid >> 5;
    int bc = blockIdx.x;
    int c  = bc & (Cn-1);

    if (tid < 64) {
        float ang = 2.0f*3.14159265358979323846f*(float)tid/128.0f;    // +angle = conj
        float s_, c_; sincosf(ang, &s_, &c_);
        tw[tid] = make_float2(c_, s_);
    }
    if (tid < NBn) a6[tid] = g_alpha[bc*NBn + tid];
    if (tid < 9)   cw[tid] = conv_w[c*9 + tid];
    int kxi = g_kxi, kyi = g_kyi;
    __syncthreads();
    LaneTw T = load_lane_tw(tw, l);

    // ---- gated spectrum into Z (natural h, compressed cc; addr == linear index)
    #pragma unroll
    for (int it = 0; it < (Fn + NT-1)/NT; it++) {
        int i = tid + it*NT;
        if (i < Fn) {
            int h = i / 65, cc = i - h*65;
            int kk = (cc == 64) ? 64 : brev7(2*cc);
            float al = a6[g_bandid[i]];
            float2 z;
            if (h < kxi && kk < kyi) {
                z = g_Xm[(size_t)bc*Fn + i];
                z.x *= al; z.y *= al;
            } else {
                z = g_Xf[(size_t)bc*Fn + i];
                float om = 1.0f - al;
                z.x *= om; z.y *= om;
            }
            Z[i] = z;
        }
    }
    __syncthreads();

    // ---- inverse column FFTs (DIF, conj twiddles): natural in, brev-stored out
    for (int cc = w; cc < 65; cc += 16) {
        float2 x0 = Z[(l      )*P + cc];
        float2 x1 = Z[(32 + l )*P + cc];
        float2 x2 = Z[(64 + l )*P + cc];
        float2 x3 = Z[(96 + l )*P + cc];
        fft128_dif(x0, x1, x2, x3, T, l);
        Z[(l      )*P + cc] = x0;
        Z[(32 + l )*P + cc] = x1;
        Z[(64 + l )*P + cc] = x2;
        Z[(96 + l )*P + cc] = x3;
    }
    __syncthreads();

    // ---- inverse row FFTs (DIT, conj): hermitian gather -> natural time out
    const float sc = 1.0f/128.0f;
    const float* xt0 = g_xt + (size_t)bc*HWn;
    float* sp0 = g_spec + (size_t)bc*HWn;
    #pragma unroll
    for (int i = 0; i < 8; i++) {
        int r = w + 16*i;
        const float2* zrow = Z + brev7(r)*P;   // holds this row's spectral data
        float2 xr[4];
        #pragma unroll
        for (int q = 0; q < 4; q++) {
            int n = 32*q + l;
            int k = brev7(n);                  // DIT input position n needs K[brev(n)]
            float2 v;
            if (k < 64)       v = zrow[n >> 1];           // n even
            else if (k == 64) v = zrow[64];               // n == 1
            else { int cc2 = brev7(128 - k) >> 1; v = zrow[cc2]; v.y = -v.y; }
            xr[q] = v;
        }
        fft128_dit(xr[0], xr[1], xr[2], xr[3], T, l);
        // extract Re * sc + depthwise conv, write g_spec
        #pragma unroll
        for (int q = 0; q < 4; q++) {
            int wc = 32*q + l;
            float v = xr[q].x * sc;
            float cacc = 0.f;
            #pragma unroll
            for (int dy = -1; dy <= 1; dy++) {
                int hh = r + dy;
                if (hh < 0 || hh >= Hn) continue;
                #pragma unroll
                for (int dx = -1; dx <= 1; dx++) {
                    int ww = wc + dx;
                    if (ww >= 0 && ww < Wn)
                        cacc += cw[(dy+1)*3 + (dx+1)] * xt0[hh*Wn + ww];
                }
            }
            sp0[r*128 + wc] = v + cacc;
        }
    }
}

// ---------------- K4: pointwise GEMM (FFMA2) + spec add + conditional LN ------
#define XS_STRIDE 66
__global__ void k4_final(const float* __restrict__ x,   const float* __restrict__ lin_b,
                         const float* __restrict__ tme,
                         const float* __restrict__ nww, const float* __restrict__ nwb,
                         const float* __restrict__ nbw, const float* __restrict__ nbb,
                         float* __restrict__ out) {
    extern __shared__ float sm[];
    float* xs  = sm;                       // [256][XS_STRIDE]
    float* ss  = sm + Cn*XS_STRIDE;        // [256][65]
    float* wsm = ss + Cn*65;               // [32][256]
    int tid = threadIdx.x;
    int b  = blockIdx.x >> 8;
    int p0 = (blockIdx.x & 255) << 6;

    for (int i = tid; i < 64*Cn; i += 256) {
        int pi = i >> 8, c = i & 255;
        xs[c*XS_STRIDE + pi] = x[((size_t)b*HWn + p0 + pi)*Cn + c];
    }
    for (int i = tid; i < Cn*64; i += 256) {
        int c = i >> 6, pi = i & 63;
        ss[c*65 + pi] = g_spec[((size_t)(b*Cn + c))*HWn + p0 + pi];
    }
    __syncthreads();

    int tc = tid & 31, tp = tid >> 5;
    u64 acc2[8][4];
    #pragma unroll
    for (int q = 0; q < 8; q++) {
        int cq = tc + 32*q;
        float lb = lin_b[cq];
        #pragma unroll
        for (int rp = 0; rp < 4; rp++)
            acc2[q][rp] = pk2(lb + ss[cq*65 + tp*8 + 2*rp],
                              lb + ss[cq*65 + tp*8 + 2*rp + 1]);
    }

    for (int d0 = 0; d0 < Cn; d0 += 32) {
        __syncthreads();
        for (int i = tid; i < 32*Cn; i += 256)
            wsm[i] = g_lwT[(size_t)d0*Cn + i];
        __syncthreads();
        #pragma unroll 4
        for (int dd = 0; dd < 32; dd++) {
            int d = d0 + dd;
            const u64* xp = (const u64*)&xs[d*XS_STRIDE + tp*8];
            u64 xv2[4];
            #pragma unroll
            for (int rp = 0; rp < 4; rp++) xv2[rp] = xp[rp];
            #pragma unroll
            for (int q = 0; q < 8; q++) {
                float wv = wsm[dd*Cn + tc + 32*q];
                u64 w2 = pk2(wv, wv);
                #pragma unroll
                for (int rp = 0; rp < 4; rp++)
                    FMA2(acc2[q][rp], w2, xv2[rp], acc2[q][rp]);
            }
        }
    }

    float acc8[8][8];
    #pragma unroll
    for (int q = 0; q < 8; q++)
        #pragma unroll
        for (int rp = 0; rp < 4; rp++) {
            float2 v = upk2(acc2[q][rp]);
            acc8[q][2*rp]   = v.x;
            acc8[q][2*rp+1] = v.y;
        }

    float psum[8], psq[8];
    #pragma unroll
    for (int r = 0; r < 8; r++) { psum[r] = 0.f; psq[r] = 0.f; }
    #pragma unroll
    for (int q = 0; q < 8; q++)
        #pragma unroll
        for (int r = 0; r < 8; r++) {
            psum[r] += acc8[q][r];
            psq[r]  += acc8[q][r]*acc8[q][r];
        }
    #pragma unroll
    for (int off = 16; off > 0; off >>= 1)
        #pragma unroll
        for (int r = 0; r < 8; r++) {
            psum[r] += __shfl_xor_sync(0xffffffffu, psum[r], off);
            psq[r]  += __shfl_xor_sync(0xffffffffu, psq[r],  off);
        }
    float mean[8], rstd[8];
    #pragma unroll
    for (int r = 0; r < 8; r++) {
        mean[r] = psum[r] * (1.0f/256.0f);
        float var = psq[r] * (1.0f/256.0f) - mean[r]*mean[r];
        rstd[r] = rsqrtf(var + 1e-5f);
    }
    float t = tme[b];
    #pragma unroll
    for (int q = 0; q < 8; q++) {
        int cq = tc + 32*q;
        float wc = t * nww[cq] + nwb[cq];
        float bc_ = t * nbw[cq] + nbb[cq];
        #pragma unroll
        for (int r = 0; r < 8; r++) {
            int pi = tp*8 + r;
            out[((size_t)(b*HWn + p0 + pi))*Cn + cq] =
                wc * (acc8[q][r] - mean[r]) * rstd[r] + bc_;
        }
    }
}

// ------------------------------- launch ---------------------------------------
extern "C" void kernel_launch(void* const* d_in, const int* in_sizes, int n_in,
                              void* d_out, int out_size) {
    const float* x      = (const float*)d_in[0];
    const float* tme    = (const float*)d_in[1];
    const float* w_real = (const float*)d_in[2];
    const float* w_imag = (const float*)d_in[3];
    const float* conv_w = (const float*)d_in[4];
    const float* lin_w  = (const float*)d_in[5];
    const float* lin_b  = (const float*)d_in[6];
    const float* mlp_w1 = (const float*)d_in[7];
    const float* mlp_b1 = (const float*)d_in[8];
    const float* mlp_w2 = (const float*)d_in[9];
    const float* mlp_b2 = (const float*)d_in[10];
    const float* nww    = (const float*)d_in[11];
    const float* nwb    = (const float*)d_in[12];
    const float* nbw    = (const float*)d_in[13];
    const float* nbb    = (const float*)d_in[14];
    const float* kx     = (const float*)d_in[15];
    const float* ky     = (const float*)d_in[16];
    float* out = (float*)d_out;

    const int smem_fft = 128*P*8;                                       // 66,560 B
    const int smem_k4  = (Cn*XS_STRIDE + Cn*65 + 32*Cn) * 4;            // 166,912 B
    cudaFuncSetAttribute(k1_fft,  cudaFuncAttributeMaxDynamicSharedMemorySize, smem_fft);
    cudaFuncSetAttribute(k3_ifft, cudaFuncAttributeMaxDynamicSharedMemorySize, smem_fft);
    cudaFuncSetAttribute(k4_final, cudaFuncAttributeMaxDynamicSharedMemorySize, smem_k4);

    k0_bands<<<1, 256>>>(kx, ky);
    k_trw<<<dim3(8,8), dim3(32,8)>>>(lin_w);

    dim3 trg(Cn/32, HWn/32, Bn);
    k_tr<<<trg, dim3(32,8)>>>(x);

    k1_fft<<<Bn*Cn, NT, smem_fft>>>(mlp_w1, mlp_b1, mlp_w2, mlp_b2);

    dim3 mixg(Cn/32, (Bn*Fn + 31)/32);
    k2b_mix<<<mixg, 256>>>(w_real, w_imag);

    k3_ifft<<<Bn*Cn, NT, smem_fft>>>(conv_w);

    k4_final<<<Bn*(HWn/64), 256, smem_k4>>>(x, lin_b, tme, nww, nwb, nbw, nbb, out);
}